// round 9
// baseline (speedup 1.0000x reference)
#include <cuda_runtime.h>
#include <cstdint>

#define NN 100000
#define NE 1250000
#define FS 68

// ---------------- device scratch (no allocs allowed) ----------------
__device__ __align__(16) float g_wp[(size_t)NE * 64];    // per-edge weights, BINNED by dst
__device__ int g_srcp[NE];                               // src node per binned position
__device__ int g_invperm[NE];                            // edge -> binned position
__device__ int g_degi[NN];                               // zero before each replay (tail)
__device__ int g_start[NN];
__device__ int g_cursor[NN];                             // zero before each replay (tail)
__device__ int g_bsum[128];
__device__ int g_idx64;

// pre-converted tf32 weights
__device__ uint32_t g_fw1u[1024];    // [64][16] padded
__device__ uint32_t g_fw2u[4096];
__device__ uint32_t g_fw3u[4096];
__device__ uint32_t g_wigu[4096];
__device__ uint32_t g_wihu[12288];
__device__ uint32_t g_whhu[12288];

__device__ __forceinline__ float sigm(float x) { return 1.f / (1.f + expf(-x)); }

__device__ __forceinline__ uint32_t f2tf32(float x) {
    uint32_t u;
    asm("cvt.rna.tf32.f32 %0, %1;" : "=r"(u) : "f"(x));
    return u;
}

// D[m][n] = sum_k A[m][k] * W[n][k], m16n8k8 tf32
__device__ __forceinline__ void mma_tf32(float& c0, float& c1, float& c2, float& c3,
                                         uint32_t a0, uint32_t a1, uint32_t a2, uint32_t a3,
                                         uint32_t b0, uint32_t b1)
{
    asm volatile("mma.sync.aligned.m16n8k8.row.col.f32.tf32.tf32.f32 "
                 "{%0,%1,%2,%3}, {%4,%5,%6,%7}, {%8,%9}, {%0,%1,%2,%3};"
                 : "+f"(c0), "+f"(c1), "+f"(c2), "+f"(c3)
                 : "r"(a0), "r"(a1), "r"(a2), "r"(a3), "r"(b0), "r"(b1));
}

// ---------------- launch 1: prep (+ edge_index dtype detect in block 0) ----------------
__global__ void prep_kernel(const float* __restrict__ fW1, const float* __restrict__ fW2,
                            const float* __restrict__ fW3, const float* __restrict__ Wig,
                            const float* __restrict__ Wih, const float* __restrict__ Whh,
                            const int* __restrict__ eidx_raw)
{
    int i = blockIdx.x * blockDim.x + threadIdx.x;
    if (blockIdx.x == 0) {
        __shared__ int nz;
        if (threadIdx.x == 0) nz = 0;
        __syncthreads();
        if (eidx_raw[2 * threadIdx.x + 1] != 0) atomicOr(&nz, 1);
        __syncthreads();
        if (threadIdx.x == 0) g_idx64 = (nz == 0) ? 1 : 0;
    }
    if (i < 1024) {
        int o = i >> 4, k = i & 15;
        g_fw1u[i] = (k < 13) ? f2tf32(fW1[o * 13 + k]) : 0u;
    }
    if (i < 4096) {
        g_fw2u[i] = f2tf32(fW2[i]);
        g_fw3u[i] = f2tf32(fW3[i]);
        g_wigu[i] = f2tf32(Wig[i]);
    }
    if (i < 12288) {
        g_wihu[i] = f2tf32(Wih[i]);
        g_whhu[i] = f2tf32(Whh[i]);
    }
}

// ---------------- launch 2: copy hx + degree count (g_degi pre-zeroed by tail) ----------------
__global__ void copy_hx_degi_kernel(const float* __restrict__ hx, float* __restrict__ out,
                                    const void* __restrict__ eidx, int N, int E)
{
    int idx = blockIdx.x * blockDim.x + threadIdx.x;
    if (idx < N * 64) {
        int n = idx >> 6, k = idx & 63;
        out[(size_t)n * 256 + k] = hx[idx];
    }
    if (idx < E) {
        int d;
        if (g_idx64) d = (int)((const long long*)eidx)[idx];
        else         d = ((const int*)eidx)[idx];
        atomicAdd(&g_degi[d], 1);
    }
}

// ---------------- launch 3: per-1024-element block scan ----------------
__global__ void scan1_kernel(int N) {
    __shared__ int sS[256];
    int b = blockIdx.x, tid = threadIdx.x;
    int base = b * 1024 + tid * 4;
    int v0 = (base + 0 < N) ? g_degi[base + 0] : 0;
    int v1 = (base + 1 < N) ? g_degi[base + 1] : 0;
    int v2 = (base + 2 < N) ? g_degi[base + 2] : 0;
    int v3 = (base + 3 < N) ? g_degi[base + 3] : 0;
    int tsum = v0 + v1 + v2 + v3;
    sS[tid] = tsum;
    __syncthreads();
    for (int off = 1; off < 256; off <<= 1) {
        int x = (tid >= off) ? sS[tid - off] : 0;
        __syncthreads();
        sS[tid] += x;
        __syncthreads();
    }
    int excl = sS[tid] - tsum;
    if (base + 0 < N) g_start[base + 0] = excl;
    if (base + 1 < N) g_start[base + 1] = excl + v0;
    if (base + 2 < N) g_start[base + 2] = excl + v0 + v1;
    if (base + 3 < N) g_start[base + 3] = excl + v0 + v1 + v2;
    if (tid == 255) g_bsum[b] = sS[255];
}

// ---------------- launch 4: add cross-block prefix (inline, no scan2) ----------------
__global__ void scan3_kernel(int N) {
    __shared__ int soff;
    int b = blockIdx.x;
    int grp = b >> 2;            // each 256-thread block lies in one 1024-group
    if (threadIdx.x < 32) {
        int acc = 0;
        for (int j = threadIdx.x; j < grp; j += 32) acc += g_bsum[j];
        #pragma unroll
        for (int m = 16; m; m >>= 1) acc += __shfl_xor_sync(0xffffffffu, acc, m);
        if (threadIdx.x == 0) soff = acc;
    }
    __syncthreads();
    int i = b * 256 + threadIdx.x;
    if (i < N) g_start[i] += soff;
}

// ---------------- launch 5: bin edges by destination ----------------
__global__ void bin_kernel(const void* __restrict__ eidx, int E) {
    int e = blockIdx.x * blockDim.x + threadIdx.x;
    if (e >= E) return;
    int d, s;
    if (g_idx64) {
        const long long* p = (const long long*)eidx;
        d = (int)p[e]; s = (int)p[E + e];
    } else {
        const int* p = (const int*)eidx;
        d = p[e]; s = p[E + e];
    }
    int pos = g_start[d] + atomicAdd(&g_cursor[d], 1);
    g_invperm[e] = pos;
    g_srcp[pos] = s;
}

// ---------------- launch 6 (PROFILED): fnet via mma.sync tf32 ----------------
// Block: 256 threads (8 warps), 128 edges, 2 blocks/SM. In-place layers per warp.
#define F_X   0
#define F_W1  (128 * FS)              /* 8704  */
#define F_W2  (F_W1 + 64 * 20)        /* 9984  */
#define F_W3  (F_W2 + 64 * FS)        /* 14336 */
#define F_B   (F_W3 + 64 * FS)        /* 18688 */
#define F_P   (F_B + 192)             /* 18880 */
#define FNET_FLOATS (F_P + 128)       /* 19008 */
#define FNET_SMEM (FNET_FLOATS * 4)   /* 76032 B -> 2 blocks/SM */

__global__ __launch_bounds__(256, 2) void fnet_mma_kernel(
    const float* __restrict__ ef,
    const float* __restrict__ fb1, const float* __restrict__ fb2,
    const float* __restrict__ fb3, int E)
{
    extern __shared__ float sm[];
    uint32_t* uX  = (uint32_t*)(sm + F_X);
    uint32_t* uW1 = (uint32_t*)(sm + F_W1);   // stride 20
    uint32_t* uW2 = (uint32_t*)(sm + F_W2);
    uint32_t* uW3 = (uint32_t*)(sm + F_W3);
    float*    sB  = sm + F_B;
    int*      sP  = (int*)(sm + F_P);

    const int tid = threadIdx.x;
    const int wid = tid >> 5, lane = tid & 31;
    const int g = lane >> 2, q = lane & 3;
    const int e0 = blockIdx.x * 128;
    const int r0 = wid * 16;
    const int rA = r0 + g, rB = r0 + 8 + g;

    for (int idx = tid; idx < 128 * 16; idx += 256) {
        int e = idx >> 4, k = idx & 15;
        float v = (k < 13 && e0 + e < E) ? ef[(size_t)(e0 + e) * 13 + k] : 0.f;
        uX[e * FS + k] = f2tf32(v);
    }
    if (tid < 128) sP[tid] = (e0 + tid < E) ? g_invperm[e0 + tid] : -1;
    for (int idx = tid; idx < 1024; idx += 256) {
        int o = idx >> 4, k = idx & 15;
        uW1[o * 20 + k] = g_fw1u[idx];
    }
    for (int idx = tid; idx < 4096; idx += 256) {
        int o = idx >> 6, k = idx & 63;
        uW2[o * FS + k] = g_fw2u[idx];
        uW3[o * FS + k] = g_fw3u[idx];
    }
    if (tid < 64) { sB[tid] = fb1[tid]; sB[64 + tid] = fb2[tid]; sB[128 + tid] = fb3[tid]; }
    __syncthreads();

    float acc[8][4];

    // ---- layer 1 (K = 16) ----
    #pragma unroll
    for (int j = 0; j < 8; j++) {
        int cb = j * 8 + 2 * q;
        acc[j][0] = acc[j][2] = sB[cb];
        acc[j][1] = acc[j][3] = sB[cb + 1];
    }
    #pragma unroll
    for (int k0 = 0; k0 < 2; k0++) {
        uint32_t a0 = uX[rA * FS + 8 * k0 + q];
        uint32_t a1 = uX[rB * FS + 8 * k0 + q];
        uint32_t a2 = uX[rA * FS + 8 * k0 + q + 4];
        uint32_t a3 = uX[rB * FS + 8 * k0 + q + 4];
        #pragma unroll
        for (int j = 0; j < 8; j++) {
            uint32_t b0 = uW1[(8 * j + g) * 20 + 8 * k0 + q];
            uint32_t b1 = uW1[(8 * j + g) * 20 + 8 * k0 + q + 4];
            mma_tf32(acc[j][0], acc[j][1], acc[j][2], acc[j][3], a0, a1, a2, a3, b0, b1);
        }
    }
    #pragma unroll
    for (int j = 0; j < 8; j++) {
        int cb = j * 8 + 2 * q;
        uX[rA * FS + cb]     = f2tf32(fmaxf(acc[j][0], 0.f));
        uX[rA * FS + cb + 1] = f2tf32(fmaxf(acc[j][1], 0.f));
        uX[rB * FS + cb]     = f2tf32(fmaxf(acc[j][2], 0.f));
        uX[rB * FS + cb + 1] = f2tf32(fmaxf(acc[j][3], 0.f));
    }
    __syncwarp();

    // ---- layer 2 (K = 64, relu) ----
    #pragma unroll
    for (int j = 0; j < 8; j++) {
        int cb = j * 8 + 2 * q;
        acc[j][0] = acc[j][2] = sB[64 + cb];
        acc[j][1] = acc[j][3] = sB[64 + cb + 1];
    }
    #pragma unroll
    for (int k0 = 0; k0 < 8; k0++) {
        uint32_t a0 = uX[rA * FS + 8 * k0 + q];
        uint32_t a1 = uX[rB * FS + 8 * k0 + q];
        uint32_t a2 = uX[rA * FS + 8 * k0 + q + 4];
        uint32_t a3 = uX[rB * FS + 8 * k0 + q + 4];
        #pragma unroll
        for (int j = 0; j < 8; j++) {
            uint32_t b0 = uW2[(8 * j + g) * FS + 8 * k0 + q];
            uint32_t b1 = uW2[(8 * j + g) * FS + 8 * k0 + q + 4];
            mma_tf32(acc[j][0], acc[j][1], acc[j][2], acc[j][3], a0, a1, a2, a3, b0, b1);
        }
    }
    __syncwarp();
    #pragma unroll
    for (int j = 0; j < 8; j++) {
        int cb = j * 8 + 2 * q;
        uX[rA * FS + cb]     = f2tf32(fmaxf(acc[j][0], 0.f));
        uX[rA * FS + cb + 1] = f2tf32(fmaxf(acc[j][1], 0.f));
        uX[rB * FS + cb]     = f2tf32(fmaxf(acc[j][2], 0.f));
        uX[rB * FS + cb + 1] = f2tf32(fmaxf(acc[j][3], 0.f));
    }
    __syncwarp();

    // ---- layer 3 (K = 64, no relu, fp32 out) ----
    #pragma unroll
    for (int j = 0; j < 8; j++) {
        int cb = j * 8 + 2 * q;
        acc[j][0] = acc[j][2] = sB[128 + cb];
        acc[j][1] = acc[j][3] = sB[128 + cb + 1];
    }
    #pragma unroll
    for (int k0 = 0; k0 < 8; k0++) {
        uint32_t a0 = uX[rA * FS + 8 * k0 + q];
        uint32_t a1 = uX[rB * FS + 8 * k0 + q];
        uint32_t a2 = uX[rA * FS + 8 * k0 + q + 4];
        uint32_t a3 = uX[rB * FS + 8 * k0 + q + 4];
        #pragma unroll
        for (int j = 0; j < 8; j++) {
            uint32_t b0 = uW3[(8 * j + g) * FS + 8 * k0 + q];
            uint32_t b1 = uW3[(8 * j + g) * FS + 8 * k0 + q + 4];
            mma_tf32(acc[j][0], acc[j][1], acc[j][2], acc[j][3], a0, a1, a2, a3, b0, b1);
        }
    }
    __syncwarp();
    {
        float* sX = sm + F_X;
        #pragma unroll
        for (int j = 0; j < 8; j++) {
            int cb = j * 8 + 2 * q;
            sX[rA * FS + cb]     = acc[j][0];
            sX[rA * FS + cb + 1] = acc[j][1];
            sX[rB * FS + cb]     = acc[j][2];
            sX[rB * FS + cb + 1] = acc[j][3];
        }
    }
    __syncthreads();

    // store rows to their BINNED positions in g_wp
    {
        const float* sX = sm + F_X;
        #pragma unroll
        for (int i = 0; i < 8; i++) {
            int gidx = i * 256 + tid;       // 0..2047 float4s
            int r = gidx >> 4, c4 = gidx & 15;
            int dst = sP[r];
            if (dst >= 0)
                ((float4*)g_wp)[(size_t)dst * 16 + c4] = *(const float4*)(sX + r * FS + c4 * 4);
        }
    }
}

// ---------------- launches 7-9: fused agg + GRU node update (R5 structure) ----------------
#define N_UHX  0
#define N_HX32 (N_UHX + 64 * FS)
#define N_UINP (N_HX32 + 64 * FS)
#define N_W    (N_UINP + 64 * FS)
#define N_AGG  (N_W + 2 * 64 * FS)
#define N_BIG  (N_AGG + 64 * FS)
#define N_BIH  (N_BIG + 64)
#define N_BHH  (N_BIH + 192)
#define N_RED  (N_BHH + 192)
#define N_STAT (N_RED + 1024)
#define NODE_FLOATS (N_STAT + 256)
#define NODE_SMEM (NODE_FLOATS * 4)

__global__ __launch_bounds__(512, 1) void node_mma_kernel(
    float* __restrict__ out,
    const float* __restrict__ bih, const float* __restrict__ bhh,
    const float* __restrict__ big, int t, int N)
{
    extern __shared__ float sm[];
    uint32_t* uHx   = (uint32_t*)(sm + N_UHX);
    float*    sHx32 = sm + N_HX32;
    uint32_t* uInp  = (uint32_t*)(sm + N_UINP);
    float*    sOut  = sm + N_UINP;
    uint32_t* uW    = (uint32_t*)(sm + N_W);
    float*    sAgg  = sm + N_AGG;
    float*    sBig  = sm + N_BIG;
    float*    sBih  = sm + N_BIH;
    float*    sBhh  = sm + N_BHH;
    float*    sRed  = sm + N_RED;
    float*    sStat = sm + N_STAT;

    const int tx = threadIdx.x;
    const int wid = tx >> 5, lane = tx & 31;
    const int g = lane >> 2, q = lane & 3;
    const int rowgrp = wid & 3, qt = wid >> 2;
    const int nq = qt * 16;
    const int n0 = blockIdx.x * 64;
    const int toff = t * 64;
    const int rA = rowgrp * 16 + g, rB = rA + 8;
    const int gnA = n0 + rA, gnB = n0 + rB;

    // ---- stage hx + Wig + biases ----
    for (int idx = tx; idx < 4096; idx += 512) {
        int n = idx >> 6, k = idx & 63;
        float v = (n0 + n < N) ? out[(size_t)(n0 + n) * 256 + toff + k] : 0.f;
        sHx32[n * FS + k] = v;
        uHx[n * FS + k] = f2tf32(v);
        uW[(idx >> 6) * FS + (idx & 63)] = g_wigu[idx];
    }
    if (tx < 64)  sBig[tx] = big[tx];
    if (tx < 192) { sBih[tx] = bih[tx]; sBhh[tx] = bhh[tx]; }

    // ---- in-block aggregation: warp wid owns nodes wid*4 .. wid*4+3 ----
    // unroll-4; all four src indices loaded up-front (independent of data loads)
    {
        const float* o_t = out + toff;
        #pragma unroll
        for (int u = 0; u < 4; u++) {
            int ln = wid * 4 + u;
            int gn = n0 + ln;
            float ax = 0.f, ay = 0.f, bx = 0.f, by = 0.f;
            float cx = 0.f, cy = 0.f, dx = 0.f, dy = 0.f;
            if (gn < N) {
                int start = g_start[gn];
                int deg   = g_degi[gn];
                int i = 0;
                #pragma unroll 1
                for (; i + 4 <= deg; i += 4) {
                    int p = start + i;
                    int s0 = g_srcp[p],     s1 = g_srcp[p + 1];
                    int s2 = g_srcp[p + 2], s3 = g_srcp[p + 3];
                    float2 w0 = *(const float2*)(g_wp + (size_t)p * 64 + 2 * lane);
                    float2 h0 = *(const float2*)(o_t + (size_t)s0 * 256 + 2 * lane);
                    float2 w1 = *(const float2*)(g_wp + (size_t)(p + 1) * 64 + 2 * lane);
                    float2 h1 = *(const float2*)(o_t + (size_t)s1 * 256 + 2 * lane);
                    float2 wv = *(const float2*)(g_wp + (size_t)(p + 2) * 64 + 2 * lane);
                    float2 h2 = *(const float2*)(o_t + (size_t)s2 * 256 + 2 * lane);
                    float2 w3 = *(const float2*)(g_wp + (size_t)(p + 3) * 64 + 2 * lane);
                    float2 h3 = *(const float2*)(o_t + (size_t)s3 * 256 + 2 * lane);
                    ax += w0.x * h0.x; ay += w0.y * h0.y;
                    bx += w1.x * h1.x; by += w1.y * h1.y;
                    cx += wv.x * h2.x; cy += wv.y * h2.y;
                    dx += w3.x * h3.x; dy += w3.y * h3.y;
                }
                #pragma unroll 1
                for (; i < deg; i++) {
                    int p = start + i;
                    int s0 = g_srcp[p];
                    float2 w0 = *(const float2*)(g_wp + (size_t)p * 64 + 2 * lane);
                    float2 h0 = *(const float2*)(o_t + (size_t)s0 * 256 + 2 * lane);
                    ax += w0.x * h0.x; ay += w0.y * h0.y;
                }
            }
            sAgg[ln * FS + 2 * lane]     = (ax + bx) + (cx + dx);
            sAgg[ln * FS + 2 * lane + 1] = (ay + by) + (cy + dy);
        }
    }
    __syncthreads();

    // ---- inp = sigmoid(hx @ Wig^T + big) * agg * invdeg ----
    {
        float aw[2][4];
        #pragma unroll
        for (int j = 0; j < 2; j++) {
            int cb = nq + 8 * j + 2 * q;
            aw[j][0] = aw[j][2] = sBig[cb];
            aw[j][1] = aw[j][3] = sBig[cb + 1];
        }
        #pragma unroll
        for (int k0 = 0; k0 < 8; k0++) {
            uint32_t a0 = uHx[rA * FS + 8 * k0 + q];
            uint32_t a1 = uHx[rB * FS + 8 * k0 + q];
            uint32_t a2 = uHx[rA * FS + 8 * k0 + q + 4];
            uint32_t a3 = uHx[rB * FS + 8 * k0 + q + 4];
            #pragma unroll
            for (int j = 0; j < 2; j++) {
                uint32_t b0 = uW[(nq + 8 * j + g) * FS + 8 * k0 + q];
                uint32_t b1 = uW[(nq + 8 * j + g) * FS + 8 * k0 + q + 4];
                mma_tf32(aw[j][0], aw[j][1], aw[j][2], aw[j][3], a0, a1, a2, a3, b0, b1);
            }
        }
        float invA = (gnA < N) ? 1.f / fmaxf((float)g_degi[gnA], 1.f) : 0.f;
        float invB = (gnB < N) ? 1.f / fmaxf((float)g_degi[gnB], 1.f) : 0.f;
        #pragma unroll
        for (int j = 0; j < 2; j++) {
            int cb = nq + 8 * j + 2 * q;
            uInp[rA * FS + cb]     = f2tf32(sigm(aw[j][0]) * sAgg[rA * FS + cb]     * invA);
            uInp[rA * FS + cb + 1] = f2tf32(sigm(aw[j][1]) * sAgg[rA * FS + cb + 1] * invA);
            uInp[rB * FS + cb]     = f2tf32(sigm(aw[j][2]) * sAgg[rB * FS + cb]     * invB);
            uInp[rB * FS + cb + 1] = f2tf32(sigm(aw[j][3]) * sAgg[rB * FS + cb + 1] * invB);
        }
    }
    __syncthreads();

    // ---- GI = inp @ Wih^T ; GH = hx @ Whh^T : register accumulators ----
    float accI[3][2][4], accH[3][2][4];
    for (int c = 0; c < 3; c++) {
        for (int idx = tx; idx < 4096; idx += 512) {
            int o = idx >> 6, k = idx & 63;
            uW[o * FS + k]        = g_wihu[c * 4096 + idx];
            uW[4352 + o * FS + k] = g_whhu[c * 4096 + idx];
        }
        __syncthreads();
        #pragma unroll
        for (int j = 0; j < 2; j++)
            #pragma unroll
            for (int v = 0; v < 4; v++) { accI[c][j][v] = 0.f; accH[c][j][v] = 0.f; }
        #pragma unroll
        for (int k0 = 0; k0 < 8; k0++) {
            uint32_t aI0 = uInp[rA * FS + 8 * k0 + q];
            uint32_t aI1 = uInp[rB * FS + 8 * k0 + q];
            uint32_t aI2 = uInp[rA * FS + 8 * k0 + q + 4];
            uint32_t aI3 = uInp[rB * FS + 8 * k0 + q + 4];
            uint32_t aH0 = uHx[rA * FS + 8 * k0 + q];
            uint32_t aH1 = uHx[rB * FS + 8 * k0 + q];
            uint32_t aH2 = uHx[rA * FS + 8 * k0 + q + 4];
            uint32_t aH3 = uHx[rB * FS + 8 * k0 + q + 4];
            #pragma unroll
            for (int j = 0; j < 2; j++) {
                int brow = (nq + 8 * j + g) * FS + 8 * k0 + q;
                uint32_t b0 = uW[brow], b1 = uW[brow + 4];
                mma_tf32(accI[c][j][0], accI[c][j][1], accI[c][j][2], accI[c][j][3],
                         aI0, aI1, aI2, aI3, b0, b1);
                uint32_t c0 = uW[4352 + brow], c1 = uW[4352 + brow + 4];
                mma_tf32(accH[c][j][0], accH[c][j][1], accH[c][j][2], accH[c][j][3],
                         aH0, aH1, aH2, aH3, c0, c1);
            }
        }
        __syncthreads();
    }

    // ---- instance-norm stats ----
    {
        float sIA = 0.f, qIA = 0.f, sIB = 0.f, qIB = 0.f;
        float sHA = 0.f, qHA = 0.f, sHB = 0.f, qHB = 0.f;
        #pragma unroll
        for (int c = 0; c < 3; c++)
            #pragma unroll
            for (int j = 0; j < 2; j++) {
                float a0 = accI[c][j][0], a1 = accI[c][j][1];
                float a2 = accI[c][j][2], a3 = accI[c][j][3];
                sIA += a0 + a1; qIA += a0 * a0 + a1 * a1;
                sIB += a2 + a3; qIB += a2 * a2 + a3 * a3;
                float h0 = accH[c][j][0], h1 = accH[c][j][1];
                float h2 = accH[c][j][2], h3 = accH[c][j][3];
                sHA += h0 + h1; qHA += h0 * h0 + h1 * h1;
                sHB += h2 + h3; qHB += h2 * h2 + h3 * h3;
            }
        #pragma unroll
        for (int m = 1; m <= 2; m <<= 1) {
            sIA += __shfl_xor_sync(0xffffffffu, sIA, m);
            qIA += __shfl_xor_sync(0xffffffffu, qIA, m);
            sIB += __shfl_xor_sync(0xffffffffu, sIB, m);
            qIB += __shfl_xor_sync(0xffffffffu, qIB, m);
            sHA += __shfl_xor_sync(0xffffffffu, sHA, m);
            qHA += __shfl_xor_sync(0xffffffffu, qHA, m);
            sHB += __shfl_xor_sync(0xffffffffu, sHB, m);
            qHB += __shfl_xor_sync(0xffffffffu, qHB, m);
        }
        if (q == 0) {
            float* rdA = sRed + (qt * 64 + rA) * 4;
            rdA[0] = sIA; rdA[1] = qIA; rdA[2] = sHA; rdA[3] = qHA;
            float* rdB = sRed + (qt * 64 + rB) * 4;
            rdB[0] = sIB; rdB[1] = qIB; rdB[2] = sHB; rdB[3] = qHB;
        }
    }
    __syncthreads();
    if (tx < 64) {
        float sI = 0.f, qI = 0.f, sH = 0.f, qH = 0.f;
        #pragma unroll
        for (int qt2 = 0; qt2 < 4; qt2++) {
            const float* rd = sRed + (qt2 * 64 + tx) * 4;
            sI += rd[0]; qI += rd[1]; sH += rd[2]; qH += rd[3];
        }
        float muI = sI * (1.f / 192.f);
        float varI = qI * (1.f / 192.f) - muI * muI;
        float muH = sH * (1.f / 192.f);
        float varH = qH * (1.f / 192.f) - muH * muH;
        sStat[tx * 4 + 0] = muI;
        sStat[tx * 4 + 1] = rsqrtf(varI + 1e-5f);
        sStat[tx * 4 + 2] = muH;
        sStat[tx * 4 + 3] = rsqrtf(varH + 1e-5f);
    }
    __syncthreads();

    // ---- gates + stage ----
    {
        float muIA = sStat[rA * 4 + 0], rsIA = sStat[rA * 4 + 1];
        float muHA = sStat[rA * 4 + 2], rsHA = sStat[rA * 4 + 3];
        float muIB = sStat[rB * 4 + 0], rsIB = sStat[rB * 4 + 1];
        float muHB = sStat[rB * 4 + 2], rsHB = sStat[rB * 4 + 3];
        #pragma unroll
        for (int j = 0; j < 2; j++) {
            #pragma unroll
            for (int v = 0; v < 2; v++) {
                int cb = nq + 8 * j + 2 * q + v;
                float b_r = sBih[cb],       c_r = sBhh[cb];
                float b_i = sBih[64 + cb],  c_i = sBhh[64 + cb];
                float b_n = sBih[128 + cb], c_n = sBhh[128 + cb];
                {
                    float i_r = (accI[0][j][v] - muIA) * rsIA;
                    float i_i = (accI[1][j][v] - muIA) * rsIA;
                    float i_n = (accI[2][j][v] - muIA) * rsIA;
                    float h_r = (accH[0][j][v] - muHA) * rsHA;
                    float h_i = (accH[1][j][v] - muHA) * rsHA;
                    float h_n = (accH[2][j][v] - muHA) * rsHA;
                    float r  = sigm(i_r + b_r + h_r + c_r);
                    float z  = sigm(i_i + b_i + h_i + c_i);
                    float ng = tanhf(i_n + b_n + r * (h_n + c_n));
                    float hxo = sHx32[rA * FS + cb];
                    sOut[rA * FS + cb] = ng + z * (hxo - ng);
                }
                {
                    float i_r = (accI[0][j][v + 2] - muIB) * rsIB;
                    float i_i = (accI[1][j][v + 2] - muIB) * rsIB;
                    float i_n = (accI[2][j][v + 2] - muIB) * rsIB;
                    float h_r = (accH[0][j][v + 2] - muHB) * rsHB;
                    float h_i = (accH[1][j][v + 2] - muHB) * rsHB;
                    float h_n = (accH[2][j][v + 2] - muHB) * rsHB;
                    float r  = sigm(i_r + b_r + h_r + c_r);
                    float z  = sigm(i_i + b_i + h_i + c_i);
                    float ng = tanhf(i_n + b_n + r * (h_n + c_n));
                    float hxo = sHx32[rB * FS + cb];
                    sOut[rB * FS + cb] = ng + z * (hxo - ng);
                }
            }
        }
    }
    __syncthreads();

    // ---- coalesced write of new hx ----
    for (int idx = tx; idx < 4096; idx += 512) {
        int n = idx >> 6, k = idx & 63;
        if (n0 + n < N)
            out[(size_t)(n0 + n) * 256 + toff + 64 + k] = sOut[n * FS + k];
    }
}

// ---------------- launch 10: reset counters for next replay ----------------
__global__ void tail_kernel(int N) {
    int i = blockIdx.x * blockDim.x + threadIdx.x;
    if (i < N) { g_degi[i] = 0; g_cursor[i] = 0; }
}

// ---------------- launcher ----------------
extern "C" void kernel_launch(void* const* d_in, const int* in_sizes, int n_in,
                              void* d_out, int out_size)
{
    const float* hx  = (const float*)d_in[0];
    const void*  eix = d_in[1];
    const float* ef  = (const float*)d_in[2];
    const float* fW1 = (const float*)d_in[3];
    const float* fb1 = (const float*)d_in[4];
    const float* fW2 = (const float*)d_in[5];
    const float* fb2 = (const float*)d_in[6];
    const float* fW3 = (const float*)d_in[7];
    const float* fb3 = (const float*)d_in[8];
    const float* Wih = (const float*)d_in[9];
    const float* Whh = (const float*)d_in[10];
    const float* bih = (const float*)d_in[11];
    const float* bhh = (const float*)d_in[12];
    const float* Wig = (const float*)d_in[13];
    const float* big = (const float*)d_in[14];
    float* out = (float*)d_out;

    const int N = in_sizes[0] / 64;
    const int E = in_sizes[2] / 13;
    const int nb = (N + 1023) / 1024;

    cudaFuncSetAttribute(fnet_mma_kernel, cudaFuncAttributeMaxDynamicSharedMemorySize, FNET_SMEM);
    cudaFuncSetAttribute(node_mma_kernel, cudaFuncAttributeMaxDynamicSharedMemorySize, NODE_SMEM);

    prep_kernel<<<(12288 + 255) / 256, 256>>>(fW1, fW2, fW3, Wig, Wih, Whh, (const int*)eix);
    copy_hx_degi_kernel<<<(N * 64 + 255) / 256, 256>>>(hx, out, eix, N, E);
    scan1_kernel<<<nb, 256>>>(N);
    scan3_kernel<<<(N + 255) / 256, 256>>>(N);
    bin_kernel<<<(E + 255) / 256, 256>>>(eix, E);
    fnet_mma_kernel<<<(E + 127) / 128, 256, FNET_SMEM>>>(ef, fb1, fb2, fb3, E);   // launch #6 -> profiled

    for (int t = 0; t < 3; t++)
        node_mma_kernel<<<(N + 63) / 64, 512, NODE_SMEM>>>(out, bih, bhh, big, t, N);

    tail_kernel<<<(N + 255) / 256, 256>>>(N);
}

// round 11
// speedup vs baseline: 1.1045x; 1.1045x over previous
#include <cuda_runtime.h>
#include <cuda_fp16.h>
#include <cstdint>

#define NN 100000
#define NE 1250000
#define FS 68

// ---------------- device scratch (no allocs allowed) ----------------
__device__ __align__(16) uint32_t g_wp2[(size_t)NE * 32]; // per-edge weights as half2, BINNED by dst
__device__ int g_srcp[NE];                               // src node per binned position
__device__ int g_invperm[NE];                            // edge -> binned position
__device__ int g_degi[NN];
__device__ int g_start[NN];
__device__ int g_cursor[NN];
__device__ int g_bsum[128];
__device__ int g_boff[128];
__device__ int g_idx64;

// pre-converted tf32 weights
__device__ uint32_t g_fw1u[1024];    // [64][16] padded
__device__ uint32_t g_fw2u[4096];
__device__ uint32_t g_fw3u[4096];
__device__ uint32_t g_wigu[4096];
__device__ uint32_t g_wihu[12288];
__device__ uint32_t g_whhu[12288];

__device__ __forceinline__ float sigm(float x) { return 1.f / (1.f + expf(-x)); }

__device__ __forceinline__ uint32_t f2tf32(float x) {
    uint32_t u;
    asm("cvt.rna.tf32.f32 %0, %1;" : "=r"(u) : "f"(x));
    return u;
}

// D[m][n] = sum_k A[m][k] * W[n][k], m16n8k8 tf32
__device__ __forceinline__ void mma_tf32(float& c0, float& c1, float& c2, float& c3,
                                         uint32_t a0, uint32_t a1, uint32_t a2, uint32_t a3,
                                         uint32_t b0, uint32_t b1)
{
    asm volatile("mma.sync.aligned.m16n8k8.row.col.f32.tf32.tf32.f32 "
                 "{%0,%1,%2,%3}, {%4,%5,%6,%7}, {%8,%9}, {%0,%1,%2,%3};"
                 : "+f"(c0), "+f"(c1), "+f"(c2), "+f"(c3)
                 : "r"(a0), "r"(a1), "r"(a2), "r"(a3), "r"(b0), "r"(b1));
}

// ---------------- prep: convert weights to tf32 once ----------------
__global__ void prep_kernel(const float* __restrict__ fW1, const float* __restrict__ fW2,
                            const float* __restrict__ fW3, const float* __restrict__ Wig,
                            const float* __restrict__ Wih, const float* __restrict__ Whh)
{
    int i = blockIdx.x * blockDim.x + threadIdx.x;
    if (i < 1024) {
        int o = i >> 4, k = i & 15;
        g_fw1u[i] = (k < 13) ? f2tf32(fW1[o * 13 + k]) : 0u;
    }
    if (i < 4096) {
        g_fw2u[i] = f2tf32(fW2[i]);
        g_fw3u[i] = f2tf32(fW3[i]);
        g_wigu[i] = f2tf32(Wig[i]);
    }
    if (i < 12288) {
        g_wihu[i] = f2tf32(Wih[i]);
        g_whhu[i] = f2tf32(Whh[i]);
    }
}

// ---------------- dtype detection for edge_index ----------------
__global__ void detect_kernel(const int* __restrict__ p) {
    __shared__ int nz;
    if (threadIdx.x == 0) nz = 0;
    __syncthreads();
    if (p[2 * threadIdx.x + 1] != 0) atomicOr(&nz, 1);
    __syncthreads();
    if (threadIdx.x == 0) g_idx64 = (nz == 0) ? 1 : 0;
}

// ---------------- CSR build ----------------
__global__ void copy_hx_kernel(const float* __restrict__ hx, float* __restrict__ out, int N) {
    int idx = blockIdx.x * blockDim.x + threadIdx.x;
    if (idx < N * 64) {
        int n = idx >> 6, k = idx & 63;
        out[(size_t)n * 256 + k] = hx[idx];
    }
}

__global__ void zero_cnt_kernel(int N) {
    int i = blockIdx.x * blockDim.x + threadIdx.x;
    if (i < N) { g_degi[i] = 0; g_cursor[i] = 0; }
}

__global__ void degi_kernel(const void* __restrict__ eidx, int E) {
    int e = blockIdx.x * blockDim.x + threadIdx.x;
    if (e >= E) return;
    int d;
    if (g_idx64) d = (int)((const long long*)eidx)[e];
    else         d = ((const int*)eidx)[e];
    atomicAdd(&g_degi[d], 1);
}

// per-1024-element block scan
__global__ void scan1_kernel(int N) {
    __shared__ int sS[256];
    int b = blockIdx.x, tid = threadIdx.x;
    int base = b * 1024 + tid * 4;
    int v0 = (base + 0 < N) ? g_degi[base + 0] : 0;
    int v1 = (base + 1 < N) ? g_degi[base + 1] : 0;
    int v2 = (base + 2 < N) ? g_degi[base + 2] : 0;
    int v3 = (base + 3 < N) ? g_degi[base + 3] : 0;
    int tsum = v0 + v1 + v2 + v3;
    sS[tid] = tsum;
    __syncthreads();
    for (int off = 1; off < 256; off <<= 1) {
        int x = (tid >= off) ? sS[tid - off] : 0;
        __syncthreads();
        sS[tid] += x;
        __syncthreads();
    }
    int excl = sS[tid] - tsum;
    if (base + 0 < N) g_start[base + 0] = excl;
    if (base + 1 < N) g_start[base + 1] = excl + v0;
    if (base + 2 < N) g_start[base + 2] = excl + v0 + v1;
    if (base + 3 < N) g_start[base + 3] = excl + v0 + v1 + v2;
    if (tid == 255) g_bsum[b] = sS[255];
}

__global__ void scan2_kernel(int nb) {
    if (threadIdx.x == 0) {
        int acc = 0;
        for (int i = 0; i < nb; i++) { int t = g_bsum[i]; g_boff[i] = acc; acc += t; }
    }
}

__global__ void scan3_kernel(int N) {
    int i = blockIdx.x * 256 + threadIdx.x;
    if (i < N) g_start[i] += g_boff[i >> 10];
}

__global__ void bin_kernel(const void* __restrict__ eidx, int E) {
    int e = blockIdx.x * blockDim.x + threadIdx.x;
    if (e >= E) return;
    int d, s;
    if (g_idx64) {
        const long long* p = (const long long*)eidx;
        d = (int)p[e]; s = (int)p[E + e];
    } else {
        const int* p = (const int*)eidx;
        d = p[e]; s = p[E + e];
    }
    int pos = g_start[d] + atomicAdd(&g_cursor[d], 1);
    g_invperm[e] = pos;
    g_srcp[pos] = s;
}

// ---------------- fnet via mma.sync tf32, writes binned half2 rows ----------------
#define F_X   0
#define F_W1  (256 * FS)
#define F_W2  (F_W1 + 64 * FS)
#define F_W3  (F_W2 + 64 * FS)
#define F_B   (F_W3 + 64 * FS)
#define F_P   (F_B + 192)
#define FNET_FLOATS (F_P + 256)
#define FNET_SMEM (FNET_FLOATS * 4)

__global__ __launch_bounds__(512, 1) void fnet_mma_kernel(
    const float* __restrict__ ef,
    const float* __restrict__ fb1, const float* __restrict__ fb2,
    const float* __restrict__ fb3, int E)
{
    extern __shared__ float sm[];
    uint32_t* uX  = (uint32_t*)(sm + F_X);
    uint32_t* uW1 = (uint32_t*)(sm + F_W1);
    uint32_t* uW2 = (uint32_t*)(sm + F_W2);
    uint32_t* uW3 = (uint32_t*)(sm + F_W3);
    float*    sB  = sm + F_B;
    int*      sP  = (int*)(sm + F_P);

    const int tid = threadIdx.x;
    const int wid = tid >> 5, lane = tid & 31;
    const int g = lane >> 2, q = lane & 3;
    const int e0 = blockIdx.x * 256;
    const int r0 = wid * 16;
    const int rA = r0 + g, rB = r0 + 8 + g;

    for (int idx = tid; idx < 256 * 16; idx += 512) {
        int e = idx >> 4, k = idx & 15;
        float v = (k < 13 && e0 + e < E) ? ef[(size_t)(e0 + e) * 13 + k] : 0.f;
        uX[e * FS + k] = f2tf32(v);
    }
    if (tid < 256) sP[tid] = (e0 + tid < E) ? g_invperm[e0 + tid] : -1;
    for (int idx = tid; idx < 1024; idx += 512) {
        int o = idx >> 4, k = idx & 15;
        uW1[o * FS + k] = g_fw1u[idx];
    }
    for (int idx = tid; idx < 4096; idx += 512) {
        int o = idx >> 6, k = idx & 63;
        uW2[o * FS + k] = g_fw2u[idx];
        uW3[o * FS + k] = g_fw3u[idx];
    }
    if (tid < 64) { sB[tid] = fb1[tid]; sB[64 + tid] = fb2[tid]; sB[128 + tid] = fb3[tid]; }
    __syncthreads();

    float acc[8][4];

    // ---- layer 1 (K = 16) ----
    #pragma unroll
    for (int j = 0; j < 8; j++) {
        int cb = j * 8 + 2 * q;
        acc[j][0] = acc[j][2] = sB[cb];
        acc[j][1] = acc[j][3] = sB[cb + 1];
    }
    #pragma unroll
    for (int k0 = 0; k0 < 2; k0++) {
        uint32_t a0 = uX[rA * FS + 8 * k0 + q];
        uint32_t a1 = uX[rB * FS + 8 * k0 + q];
        uint32_t a2 = uX[rA * FS + 8 * k0 + q + 4];
        uint32_t a3 = uX[rB * FS + 8 * k0 + q + 4];
        #pragma unroll
        for (int j = 0; j < 8; j++) {
            uint32_t b0 = uW1[(8 * j + g) * FS + 8 * k0 + q];
            uint32_t b1 = uW1[(8 * j + g) * FS + 8 * k0 + q + 4];
            mma_tf32(acc[j][0], acc[j][1], acc[j][2], acc[j][3], a0, a1, a2, a3, b0, b1);
        }
    }
    #pragma unroll
    for (int j = 0; j < 8; j++) {
        int cb = j * 8 + 2 * q;
        uX[rA * FS + cb]     = f2tf32(fmaxf(acc[j][0], 0.f));
        uX[rA * FS + cb + 1] = f2tf32(fmaxf(acc[j][1], 0.f));
        uX[rB * FS + cb]     = f2tf32(fmaxf(acc[j][2], 0.f));
        uX[rB * FS + cb + 1] = f2tf32(fmaxf(acc[j][3], 0.f));
    }
    __syncwarp();

    // ---- layer 2 (K = 64, relu) ----
    #pragma unroll
    for (int j = 0; j < 8; j++) {
        int cb = j * 8 + 2 * q;
        acc[j][0] = acc[j][2] = sB[64 + cb];
        acc[j][1] = acc[j][3] = sB[64 + cb + 1];
    }
    #pragma unroll
    for (int k0 = 0; k0 < 8; k0++) {
        uint32_t a0 = uX[rA * FS + 8 * k0 + q];
        uint32_t a1 = uX[rB * FS + 8 * k0 + q];
        uint32_t a2 = uX[rA * FS + 8 * k0 + q + 4];
        uint32_t a3 = uX[rB * FS + 8 * k0 + q + 4];
        #pragma unroll
        for (int j = 0; j < 8; j++) {
            uint32_t b0 = uW2[(8 * j + g) * FS + 8 * k0 + q];
            uint32_t b1 = uW2[(8 * j + g) * FS + 8 * k0 + q + 4];
            mma_tf32(acc[j][0], acc[j][1], acc[j][2], acc[j][3], a0, a1, a2, a3, b0, b1);
        }
    }
    __syncwarp();
    #pragma unroll
    for (int j = 0; j < 8; j++) {
        int cb = j * 8 + 2 * q;
        uX[rA * FS + cb]     = f2tf32(fmaxf(acc[j][0], 0.f));
        uX[rA * FS + cb + 1] = f2tf32(fmaxf(acc[j][1], 0.f));
        uX[rB * FS + cb]     = f2tf32(fmaxf(acc[j][2], 0.f));
        uX[rB * FS + cb + 1] = f2tf32(fmaxf(acc[j][3], 0.f));
    }
    __syncwarp();

    // ---- layer 3 (K = 64, no relu) ----
    #pragma unroll
    for (int j = 0; j < 8; j++) {
        int cb = j * 8 + 2 * q;
        acc[j][0] = acc[j][2] = sB[128 + cb];
        acc[j][1] = acc[j][3] = sB[128 + cb + 1];
    }
    #pragma unroll
    for (int k0 = 0; k0 < 8; k0++) {
        uint32_t a0 = uX[rA * FS + 8 * k0 + q];
        uint32_t a1 = uX[rB * FS + 8 * k0 + q];
        uint32_t a2 = uX[rA * FS + 8 * k0 + q + 4];
        uint32_t a3 = uX[rB * FS + 8 * k0 + q + 4];
        #pragma unroll
        for (int j = 0; j < 8; j++) {
            uint32_t b0 = uW3[(8 * j + g) * FS + 8 * k0 + q];
            uint32_t b1 = uW3[(8 * j + g) * FS + 8 * k0 + q + 4];
            mma_tf32(acc[j][0], acc[j][1], acc[j][2], acc[j][3], a0, a1, a2, a3, b0, b1);
        }
    }
    __syncwarp();

    // ---- epilogue: pack half2 in-place (per-warp rows, stride 68), store 128B rows ----
    {
        uint32_t* sH = (uint32_t*)(sm + F_X);
        #pragma unroll
        for (int j = 0; j < 8; j++) {
            int cw = j * 4 + q;     // half2 word index (cb/2)
            __half2 hA = __floats2half2_rn(acc[j][0], acc[j][1]);
            __half2 hB = __floats2half2_rn(acc[j][2], acc[j][3]);
            sH[rA * FS + cw] = *(uint32_t*)&hA;
            sH[rB * FS + cw] = *(uint32_t*)&hB;
        }
    }
    __syncthreads();
    {
        const uint32_t* sH = (const uint32_t*)(sm + F_X);
        #pragma unroll
        for (int i = 0; i < 4; i++) {
            int gidx = i * 512 + tid;       // 0..2047 uint4s (256 rows x 8)
            int r = gidx >> 3, c = gidx & 7;
            int dst = sP[r];
            if (dst >= 0)
                ((uint4*)g_wp2)[(size_t)dst * 8 + c] = *(const uint4*)(sH + r * FS + c * 4);
        }
    }
}

// ---------------- fused agg + GRU node update (R5 structure, half2 w) ----------------
#define N_UHX  0
#define N_HX32 (N_UHX + 64 * FS)
#define N_UINP (N_HX32 + 64 * FS)
#define N_W    (N_UINP + 64 * FS)
#define N_AGG  (N_W + 2 * 64 * FS)
#define N_BIG  (N_AGG + 64 * FS)
#define N_BIH  (N_BIG + 64)
#define N_BHH  (N_BIH + 192)
#define N_RED  (N_BHH + 192)
#define N_STAT (N_RED + 1024)
#define NODE_FLOATS (N_STAT + 256)
#define NODE_SMEM (NODE_FLOATS * 4)

__global__ __launch_bounds__(512, 1) void node_mma_kernel(
    float* __restrict__ out,
    const float* __restrict__ bih, const float* __restrict__ bhh,
    const float* __restrict__ big, int t, int N)
{
    extern __shared__ float sm[];
    uint32_t* uHx   = (uint32_t*)(sm + N_UHX);
    float*    sHx32 = sm + N_HX32;
    uint32_t* uInp  = (uint32_t*)(sm + N_UINP);
    float*    sOut  = sm + N_UINP;
    uint32_t* uW    = (uint32_t*)(sm + N_W);
    float*    sAgg  = sm + N_AGG;
    float*    sBig  = sm + N_BIG;
    float*    sBih  = sm + N_BIH;
    float*    sBhh  = sm + N_BHH;
    float*    sRed  = sm + N_RED;
    float*    sStat = sm + N_STAT;

    const int tx = threadIdx.x;
    const int wid = tx >> 5, lane = tx & 31;
    const int g = lane >> 2, q = lane & 3;
    const int rowgrp = wid & 3, qt = wid >> 2;
    const int nq = qt * 16;
    const int n0 = blockIdx.x * 64;
    const int toff = t * 64;
    const int rA = rowgrp * 16 + g, rB = rA + 8;
    const int gnA = n0 + rA, gnB = n0 + rB;

    // ---- stage hx + Wig + biases ----
    for (int idx = tx; idx < 4096; idx += 512) {
        int n = idx >> 6, k = idx & 63;
        float v = (n0 + n < N) ? out[(size_t)(n0 + n) * 256 + toff + k] : 0.f;
        sHx32[n * FS + k] = v;
        uHx[n * FS + k] = f2tf32(v);
        uW[(idx >> 6) * FS + (idx & 63)] = g_wigu[idx];
    }
    if (tx < 64)  sBig[tx] = big[tx];
    if (tx < 192) { sBih[tx] = bih[tx]; sBhh[tx] = bhh[tx]; }

    // ---- in-block aggregation: warp wid owns nodes wid*4 .. wid*4+3 (half2 w) ----
    {
        const float* o_t = out + toff;
        const __half2* w2 = (const __half2*)g_wp2;   // edge row = 32 half2
        #pragma unroll
        for (int u = 0; u < 4; u++) {
            int ln = wid * 4 + u;
            int gn = n0 + ln;
            float ax = 0.f, ay = 0.f, bx = 0.f, by = 0.f;
            if (gn < N) {
                int start = g_start[gn];
                int deg   = g_degi[gn];
                int i = 0;
                for (; i + 2 <= deg; i += 2) {
                    int p0 = start + i, p1 = start + i + 1;
                    int s0 = g_srcp[p0], s1 = g_srcp[p1];
                    float2 w0 = __half22float2(w2[(size_t)p0 * 32 + lane]);
                    float2 h0 = *(const float2*)(o_t + (size_t)s0 * 256 + 2 * lane);
                    float2 w1 = __half22float2(w2[(size_t)p1 * 32 + lane]);
                    float2 h1 = *(const float2*)(o_t + (size_t)s1 * 256 + 2 * lane);
                    ax += w0.x * h0.x; ay += w0.y * h0.y;
                    bx += w1.x * h1.x; by += w1.y * h1.y;
                }
                if (i < deg) {
                    int p0 = start + i;
                    int s0 = g_srcp[p0];
                    float2 w0 = __half22float2(w2[(size_t)p0 * 32 + lane]);
                    float2 h0 = *(const float2*)(o_t + (size_t)s0 * 256 + 2 * lane);
                    ax += w0.x * h0.x; ay += w0.y * h0.y;
                }
            }
            sAgg[ln * FS + 2 * lane]     = ax + bx;
            sAgg[ln * FS + 2 * lane + 1] = ay + by;
        }
    }
    __syncthreads();

    // ---- inp = sigmoid(hx @ Wig^T + big) * agg * invdeg ----
    {
        float aw[2][4];
        #pragma unroll
        for (int j = 0; j < 2; j++) {
            int cb = nq + 8 * j + 2 * q;
            aw[j][0] = aw[j][2] = sBig[cb];
            aw[j][1] = aw[j][3] = sBig[cb + 1];
        }
        #pragma unroll
        for (int k0 = 0; k0 < 8; k0++) {
            uint32_t a0 = uHx[rA * FS + 8 * k0 + q];
            uint32_t a1 = uHx[rB * FS + 8 * k0 + q];
            uint32_t a2 = uHx[rA * FS + 8 * k0 + q + 4];
            uint32_t a3 = uHx[rB * FS + 8 * k0 + q + 4];
            #pragma unroll
            for (int j = 0; j < 2; j++) {
                uint32_t b0 = uW[(nq + 8 * j + g) * FS + 8 * k0 + q];
                uint32_t b1 = uW[(nq + 8 * j + g) * FS + 8 * k0 + q + 4];
                mma_tf32(aw[j][0], aw[j][1], aw[j][2], aw[j][3], a0, a1, a2, a3, b0, b1);
            }
        }
        float invA = (gnA < N) ? 1.f / fmaxf((float)g_degi[gnA], 1.f) : 0.f;
        float invB = (gnB < N) ? 1.f / fmaxf((float)g_degi[gnB], 1.f) : 0.f;
        #pragma unroll
        for (int j = 0; j < 2; j++) {
            int cb = nq + 8 * j + 2 * q;
            uInp[rA * FS + cb]     = f2tf32(sigm(aw[j][0]) * sAgg[rA * FS + cb]     * invA);
            uInp[rA * FS + cb + 1] = f2tf32(sigm(aw[j][1]) * sAgg[rA * FS + cb + 1] * invA);
            uInp[rB * FS + cb]     = f2tf32(sigm(aw[j][2]) * sAgg[rB * FS + cb]     * invB);
            uInp[rB * FS + cb + 1] = f2tf32(sigm(aw[j][3]) * sAgg[rB * FS + cb + 1] * invB);
        }
    }
    __syncthreads();

    // ---- GI = inp @ Wih^T ; GH = hx @ Whh^T : register accumulators ----
    float accI[3][2][4], accH[3][2][4];
    for (int c = 0; c < 3; c++) {
        for (int idx = tx; idx < 4096; idx += 512) {
            int o = idx >> 6, k = idx & 63;
            uW[o * FS + k]        = g_wihu[c * 4096 + idx];
            uW[4352 + o * FS + k] = g_whhu[c * 4096 + idx];
        }
        __syncthreads();
        #pragma unroll
        for (int j = 0; j < 2; j++)
            #pragma unroll
            for (int v = 0; v < 4; v++) { accI[c][j][v] = 0.f; accH[c][j][v] = 0.f; }
        #pragma unroll
        for (int k0 = 0; k0 < 8; k0++) {
            uint32_t aI0 = uInp[rA * FS + 8 * k0 + q];
            uint32_t aI1 = uInp[rB * FS + 8 * k0 + q];
            uint32_t aI2 = uInp[rA * FS + 8 * k0 + q + 4];
            uint32_t aI3 = uInp[rB * FS + 8 * k0 + q + 4];
            uint32_t aH0 = uHx[rA * FS + 8 * k0 + q];
            uint32_t aH1 = uHx[rB * FS + 8 * k0 + q];
            uint32_t aH2 = uHx[rA * FS + 8 * k0 + q + 4];
            uint32_t aH3 = uHx[rB * FS + 8 * k0 + q + 4];
            #pragma unroll
            for (int j = 0; j < 2; j++) {
                int brow = (nq + 8 * j + g) * FS + 8 * k0 + q;
                uint32_t b0 = uW[brow], b1 = uW[brow + 4];
                mma_tf32(accI[c][j][0], accI[c][j][1], accI[c][j][2], accI[c][j][3],
                         aI0, aI1, aI2, aI3, b0, b1);
                uint32_t c0 = uW[4352 + brow], c1 = uW[4352 + brow + 4];
                mma_tf32(accH[c][j][0], accH[c][j][1], accH[c][j][2], accH[c][j][3],
                         aH0, aH1, aH2, aH3, c0, c1);
            }
        }
        __syncthreads();
    }

    // ---- instance-norm stats ----
    {
        float sIA = 0.f, qIA = 0.f, sIB = 0.f, qIB = 0.f;
        float sHA = 0.f, qHA = 0.f, sHB = 0.f, qHB = 0.f;
        #pragma unroll
        for (int c = 0; c < 3; c++)
            #pragma unroll
            for (int j = 0; j < 2; j++) {
                float a0 = accI[c][j][0], a1 = accI[c][j][1];
                float a2 = accI[c][j][2], a3 = accI[c][j][3];
                sIA += a0 + a1; qIA += a0 * a0 + a1 * a1;
                sIB += a2 + a3; qIB += a2 * a2 + a3 * a3;
                float h0 = accH[c][j][0], h1 = accH[c][j][1];
                float h2 = accH[c][j][2], h3 = accH[c][j][3];
                sHA += h0 + h1; qHA += h0 * h0 + h1 * h1;
                sHB += h2 + h3; qHB += h2 * h2 + h3 * h3;
            }
        #pragma unroll
        for (int m = 1; m <= 2; m <<= 1) {
            sIA += __shfl_xor_sync(0xffffffffu, sIA, m);
            qIA += __shfl_xor_sync(0xffffffffu, qIA, m);
            sIB += __shfl_xor_sync(0xffffffffu, sIB, m);
            qIB += __shfl_xor_sync(0xffffffffu, qIB, m);
            sHA += __shfl_xor_sync(0xffffffffu, sHA, m);
            qHA += __shfl_xor_sync(0xffffffffu, qHA, m);
            sHB += __shfl_xor_sync(0xffffffffu, sHB, m);
            qHB += __shfl_xor_sync(0xffffffffu, qHB, m);
        }
        if (q == 0) {
            float* rdA = sRed + (qt * 64 + rA) * 4;
            rdA[0] = sIA; rdA[1] = qIA; rdA[2] = sHA; rdA[3] = qHA;
            float* rdB = sRed + (qt * 64 + rB) * 4;
            rdB[0] = sIB; rdB[1] = qIB; rdB[2] = sHB; rdB[3] = qHB;
        }
    }
    __syncthreads();
    if (tx < 64) {
        float sI = 0.f, qI = 0.f, sH = 0.f, qH = 0.f;
        #pragma unroll
        for (int qt2 = 0; qt2 < 4; qt2++) {
            const float* rd = sRed + (qt2 * 64 + tx) * 4;
            sI += rd[0]; qI += rd[1]; sH += rd[2]; qH += rd[3];
        }
        float muI = sI * (1.f / 192.f);
        float varI = qI * (1.f / 192.f) - muI * muI;
        float muH = sH * (1.f / 192.f);
        float varH = qH * (1.f / 192.f) - muH * muH;
        sStat[tx * 4 + 0] = muI;
        sStat[tx * 4 + 1] = rsqrtf(varI + 1e-5f);
        sStat[tx * 4 + 2] = muH;
        sStat[tx * 4 + 3] = rsqrtf(varH + 1e-5f);
    }
    __syncthreads();

    // ---- gates + stage ----
    {
        float muIA = sStat[rA * 4 + 0], rsIA = sStat[rA * 4 + 1];
        float muHA = sStat[rA * 4 + 2], rsHA = sStat[rA * 4 + 3];
        float muIB = sStat[rB * 4 + 0], rsIB = sStat[rB * 4 + 1];
        float muHB = sStat[rB * 4 + 2], rsHB = sStat[rB * 4 + 3];
        #pragma unroll
        for (int j = 0; j < 2; j++) {
            #pragma unroll
            for (int v = 0; v < 2; v++) {
                int cb = nq + 8 * j + 2 * q + v;
                float b_r = sBih[cb],       c_r = sBhh[cb];
                float b_i = sBih[64 + cb],  c_i = sBhh[64 + cb];
                float b_n = sBih[128 + cb], c_n = sBhh[128 + cb];
                {
                    float i_r = (accI[0][j][v] - muIA) * rsIA;
                    float i_i = (accI[1][j][v] - muIA) * rsIA;
                    float i_n = (accI[2][j][v] - muIA) * rsIA;
                    float h_r = (accH[0][j][v] - muHA) * rsHA;
                    float h_i = (accH[1][j][v] - muHA) * rsHA;
                    float h_n = (accH[2][j][v] - muHA) * rsHA;
                    float r  = sigm(i_r + b_r + h_r + c_r);
                    float z  = sigm(i_i + b_i + h_i + c_i);
                    float ng = tanhf(i_n + b_n + r * (h_n + c_n));
                    float hxo = sHx32[rA * FS + cb];
                    sOut[rA * FS + cb] = ng + z * (hxo - ng);
                }
                {
                    float i_r = (accI[0][j][v + 2] - muIB) * rsIB;
                    float i_i = (accI[1][j][v + 2] - muIB) * rsIB;
                    float i_n = (accI[2][j][v + 2] - muIB) * rsIB;
                    float h_r = (accH[0][j][v + 2] - muHB) * rsHB;
                    float h_i = (accH[1][j][v + 2] - muHB) * rsHB;
                    float h_n = (accH[2][j][v + 2] - muHB) * rsHB;
                    float r  = sigm(i_r + b_r + h_r + c_r);
                    float z  = sigm(i_i + b_i + h_i + c_i);
                    float ng = tanhf(i_n + b_n + r * (h_n + c_n));
                    float hxo = sHx32[rB * FS + cb];
                    sOut[rB * FS + cb] = ng + z * (hxo - ng);
                }
            }
        }
    }
    __syncthreads();

    // ---- coalesced write of new hx ----
    for (int idx = tx; idx < 4096; idx += 512) {
        int n = idx >> 6, k = idx & 63;
        if (n0 + n < N)
            out[(size_t)(n0 + n) * 256 + toff + 64 + k] = sOut[n * FS + k];
    }
}

// ---------------- launcher ----------------
extern "C" void kernel_launch(void* const* d_in, const int* in_sizes, int n_in,
                              void* d_out, int out_size)
{
    const float* hx  = (const float*)d_in[0];
    const void*  eix = d_in[1];
    const float* ef  = (const float*)d_in[2];
    const float* fW1 = (const float*)d_in[3];
    const float* fb1 = (const float*)d_in[4];
    const float* fW2 = (const float*)d_in[5];
    const float* fb2 = (const float*)d_in[6];
    const float* fW3 = (const float*)d_in[7];
    const float* fb3 = (const float*)d_in[8];
    const float* Wih = (const float*)d_in[9];
    const float* Whh = (const float*)d_in[10];
    const float* bih = (const float*)d_in[11];
    const float* bhh = (const float*)d_in[12];
    const float* Wig = (const float*)d_in[13];
    const float* big = (const float*)d_in[14];
    float* out = (float*)d_out;

    const int N = in_sizes[0] / 64;
    const int E = in_sizes[2] / 13;
    const int nb = (N + 1023) / 1024;

    cudaFuncSetAttribute(fnet_mma_kernel, cudaFuncAttributeMaxDynamicSharedMemorySize, FNET_SMEM);
    cudaFuncSetAttribute(node_mma_kernel, cudaFuncAttributeMaxDynamicSharedMemorySize, NODE_SMEM);

    detect_kernel<<<1, 256>>>((const int*)eix);
    prep_kernel<<<(12288 + 255) / 256, 256>>>(fW1, fW2, fW3, Wig, Wih, Whh);
    copy_hx_kernel<<<(N * 64 + 255) / 256, 256>>>(hx, out, N);
    zero_cnt_kernel<<<(N + 255) / 256, 256>>>(N);
    degi_kernel<<<(E + 255) / 256, 256>>>(eix, E);
    scan1_kernel<<<nb, 256>>>(N);
    scan2_kernel<<<1, 32>>>(nb);
    scan3_kernel<<<(N + 255) / 256, 256>>>(N);
    bin_kernel<<<(E + 255) / 256, 256>>>(eix, E);
    fnet_mma_kernel<<<(E + 255) / 256, 512, FNET_SMEM>>>(ef, fb1, fb2, fb3, E);

    for (int t = 0; t < 3; t++)
        node_mma_kernel<<<(N + 63) / 64, 512, NODE_SMEM>>>(out, bih, bhh, big, t, N);
}

// round 12
// speedup vs baseline: 1.2121x; 1.0974x over previous
#include <cuda_runtime.h>
#include <cuda_fp16.h>
#include <cstdint>

#define NN 100000
#define NE 1250000
#define FS 68

// ---------------- device scratch (no allocs allowed) ----------------
__device__ __align__(16) uint32_t g_wp2[(size_t)NE * 32]; // per-edge weights as half2, BINNED by dst
__device__ int g_srcp[NE];                               // src node per binned position
__device__ int g_invperm[NE];                            // edge -> binned position
__device__ int g_degi[NN];
__device__ int g_start[NN];
__device__ int g_cursor[NN];
__device__ int g_bsum[128];
__device__ int g_boff[128];
__device__ int g_tilq[4];                                // persistent-kernel tile queues
__device__ int g_idx64;

// pre-converted tf32 weights
__device__ uint32_t g_fw1u[1024];    // [64][16] padded
__device__ uint32_t g_fw2u[4096];
__device__ uint32_t g_fw3u[4096];
__device__ uint32_t g_wigu[4096];
__device__ uint32_t g_wihu[12288];
__device__ uint32_t g_whhu[12288];

__device__ __forceinline__ float sigm(float x) { return 1.f / (1.f + expf(-x)); }

__device__ __forceinline__ uint32_t f2tf32(float x) {
    uint32_t u;
    asm("cvt.rna.tf32.f32 %0, %1;" : "=r"(u) : "f"(x));
    return u;
}

// D[m][n] = sum_k A[m][k] * W[n][k], m16n8k8 tf32
__device__ __forceinline__ void mma_tf32(float& c0, float& c1, float& c2, float& c3,
                                         uint32_t a0, uint32_t a1, uint32_t a2, uint32_t a3,
                                         uint32_t b0, uint32_t b1)
{
    asm volatile("mma.sync.aligned.m16n8k8.row.col.f32.tf32.tf32.f32 "
                 "{%0,%1,%2,%3}, {%4,%5,%6,%7}, {%8,%9}, {%0,%1,%2,%3};"
                 : "+f"(c0), "+f"(c1), "+f"(c2), "+f"(c3)
                 : "r"(a0), "r"(a1), "r"(a2), "r"(a3), "r"(b0), "r"(b1));
}

// ---------------- prep: convert weights to tf32 once ----------------
__global__ void prep_kernel(const float* __restrict__ fW1, const float* __restrict__ fW2,
                            const float* __restrict__ fW3, const float* __restrict__ Wig,
                            const float* __restrict__ Wih, const float* __restrict__ Whh)
{
    int i = blockIdx.x * blockDim.x + threadIdx.x;
    if (i < 1024) {
        int o = i >> 4, k = i & 15;
        g_fw1u[i] = (k < 13) ? f2tf32(fW1[o * 13 + k]) : 0u;
    }
    if (i < 4096) {
        g_fw2u[i] = f2tf32(fW2[i]);
        g_fw3u[i] = f2tf32(fW3[i]);
        g_wigu[i] = f2tf32(Wig[i]);
    }
    if (i < 12288) {
        g_wihu[i] = f2tf32(Wih[i]);
        g_whhu[i] = f2tf32(Whh[i]);
    }
}

// ---------------- dtype detection for edge_index ----------------
__global__ void detect_kernel(const int* __restrict__ p) {
    __shared__ int nz;
    if (threadIdx.x == 0) nz = 0;
    __syncthreads();
    if (p[2 * threadIdx.x + 1] != 0) atomicOr(&nz, 1);
    __syncthreads();
    if (threadIdx.x == 0) g_idx64 = (nz == 0) ? 1 : 0;
}

// ---------------- CSR build ----------------
__global__ void copy_hx_kernel(const float* __restrict__ hx, float* __restrict__ out, int N) {
    int idx = blockIdx.x * blockDim.x + threadIdx.x;
    if (idx < N * 64) {
        int n = idx >> 6, k = idx & 63;
        out[(size_t)n * 256 + k] = hx[idx];
    }
}

__global__ void zero_cnt_kernel(int N) {
    int i = blockIdx.x * blockDim.x + threadIdx.x;
    if (i < N) { g_degi[i] = 0; g_cursor[i] = 0; }
    if (i < 4) g_tilq[i] = 0;
}

__global__ void degi_kernel(const void* __restrict__ eidx, int E) {
    int e = blockIdx.x * blockDim.x + threadIdx.x;
    if (e >= E) return;
    int d;
    if (g_idx64) d = (int)((const long long*)eidx)[e];
    else         d = ((const int*)eidx)[e];
    atomicAdd(&g_degi[d], 1);
}

// per-1024-element block scan
__global__ void scan1_kernel(int N) {
    __shared__ int sS[256];
    int b = blockIdx.x, tid = threadIdx.x;
    int base = b * 1024 + tid * 4;
    int v0 = (base + 0 < N) ? g_degi[base + 0] : 0;
    int v1 = (base + 1 < N) ? g_degi[base + 1] : 0;
    int v2 = (base + 2 < N) ? g_degi[base + 2] : 0;
    int v3 = (base + 3 < N) ? g_degi[base + 3] : 0;
    int tsum = v0 + v1 + v2 + v3;
    sS[tid] = tsum;
    __syncthreads();
    for (int off = 1; off < 256; off <<= 1) {
        int x = (tid >= off) ? sS[tid - off] : 0;
        __syncthreads();
        sS[tid] += x;
        __syncthreads();
    }
    int excl = sS[tid] - tsum;
    if (base + 0 < N) g_start[base + 0] = excl;
    if (base + 1 < N) g_start[base + 1] = excl + v0;
    if (base + 2 < N) g_start[base + 2] = excl + v0 + v1;
    if (base + 3 < N) g_start[base + 3] = excl + v0 + v1 + v2;
    if (tid == 255) g_bsum[b] = sS[255];
}

__global__ void scan2_kernel(int nb) {
    if (threadIdx.x == 0) {
        int acc = 0;
        for (int i = 0; i < nb; i++) { int t = g_bsum[i]; g_boff[i] = acc; acc += t; }
    }
}

__global__ void scan3_kernel(int N) {
    int i = blockIdx.x * 256 + threadIdx.x;
    if (i < N) g_start[i] += g_boff[i >> 10];
}

__global__ void bin_kernel(const void* __restrict__ eidx, int E) {
    int e = blockIdx.x * blockDim.x + threadIdx.x;
    if (e >= E) return;
    int d, s;
    if (g_idx64) {
        const long long* p = (const long long*)eidx;
        d = (int)p[e]; s = (int)p[E + e];
    } else {
        const int* p = (const int*)eidx;
        d = p[e]; s = p[E + e];
    }
    int pos = g_start[d] + atomicAdd(&g_cursor[d], 1);
    g_invperm[e] = pos;
    g_srcp[pos] = s;
}

// ---------------- fnet via mma.sync tf32, writes binned half2 rows ----------------
#define F_X   0
#define F_W1  (256 * FS)
#define F_W2  (F_W1 + 64 * FS)
#define F_W3  (F_W2 + 64 * FS)
#define F_B   (F_W3 + 64 * FS)
#define F_P   (F_B + 192)
#define FNET_FLOATS (F_P + 256)
#define FNET_SMEM (FNET_FLOATS * 4)

__global__ __launch_bounds__(512, 1) void fnet_mma_kernel(
    const float* __restrict__ ef,
    const float* __restrict__ fb1, const float* __restrict__ fb2,
    const float* __restrict__ fb3, int E)
{
    extern __shared__ float sm[];
    uint32_t* uX  = (uint32_t*)(sm + F_X);
    uint32_t* uW1 = (uint32_t*)(sm + F_W1);
    uint32_t* uW2 = (uint32_t*)(sm + F_W2);
    uint32_t* uW3 = (uint32_t*)(sm + F_W3);
    float*    sB  = sm + F_B;
    int*      sP  = (int*)(sm + F_P);

    const int tid = threadIdx.x;
    const int wid = tid >> 5, lane = tid & 31;
    const int g = lane >> 2, q = lane & 3;
    const int e0 = blockIdx.x * 256;
    const int r0 = wid * 16;
    const int rA = r0 + g, rB = r0 + 8 + g;

    for (int idx = tid; idx < 256 * 16; idx += 512) {
        int e = idx >> 4, k = idx & 15;
        float v = (k < 13 && e0 + e < E) ? ef[(size_t)(e0 + e) * 13 + k] : 0.f;
        uX[e * FS + k] = f2tf32(v);
    }
    if (tid < 256) sP[tid] = (e0 + tid < E) ? g_invperm[e0 + tid] : -1;
    for (int idx = tid; idx < 1024; idx += 512) {
        int o = idx >> 4, k = idx & 15;
        uW1[o * FS + k] = g_fw1u[idx];
    }
    for (int idx = tid; idx < 4096; idx += 512) {
        int o = idx >> 6, k = idx & 63;
        uW2[o * FS + k] = g_fw2u[idx];
        uW3[o * FS + k] = g_fw3u[idx];
    }
    if (tid < 64) { sB[tid] = fb1[tid]; sB[64 + tid] = fb2[tid]; sB[128 + tid] = fb3[tid]; }
    __syncthreads();

    float acc[8][4];

    // ---- layer 1 (K = 16) ----
    #pragma unroll
    for (int j = 0; j < 8; j++) {
        int cb = j * 8 + 2 * q;
        acc[j][0] = acc[j][2] = sB[cb];
        acc[j][1] = acc[j][3] = sB[cb + 1];
    }
    #pragma unroll
    for (int k0 = 0; k0 < 2; k0++) {
        uint32_t a0 = uX[rA * FS + 8 * k0 + q];
        uint32_t a1 = uX[rB * FS + 8 * k0 + q];
        uint32_t a2 = uX[rA * FS + 8 * k0 + q + 4];
        uint32_t a3 = uX[rB * FS + 8 * k0 + q + 4];
        #pragma unroll
        for (int j = 0; j < 8; j++) {
            uint32_t b0 = uW1[(8 * j + g) * FS + 8 * k0 + q];
            uint32_t b1 = uW1[(8 * j + g) * FS + 8 * k0 + q + 4];
            mma_tf32(acc[j][0], acc[j][1], acc[j][2], acc[j][3], a0, a1, a2, a3, b0, b1);
        }
    }
    #pragma unroll
    for (int j = 0; j < 8; j++) {
        int cb = j * 8 + 2 * q;
        uX[rA * FS + cb]     = f2tf32(fmaxf(acc[j][0], 0.f));
        uX[rA * FS + cb + 1] = f2tf32(fmaxf(acc[j][1], 0.f));
        uX[rB * FS + cb]     = f2tf32(fmaxf(acc[j][2], 0.f));
        uX[rB * FS + cb + 1] = f2tf32(fmaxf(acc[j][3], 0.f));
    }
    __syncwarp();

    // ---- layer 2 (K = 64, relu) ----
    #pragma unroll
    for (int j = 0; j < 8; j++) {
        int cb = j * 8 + 2 * q;
        acc[j][0] = acc[j][2] = sB[64 + cb];
        acc[j][1] = acc[j][3] = sB[64 + cb + 1];
    }
    #pragma unroll
    for (int k0 = 0; k0 < 8; k0++) {
        uint32_t a0 = uX[rA * FS + 8 * k0 + q];
        uint32_t a1 = uX[rB * FS + 8 * k0 + q];
        uint32_t a2 = uX[rA * FS + 8 * k0 + q + 4];
        uint32_t a3 = uX[rB * FS + 8 * k0 + q + 4];
        #pragma unroll
        for (int j = 0; j < 8; j++) {
            uint32_t b0 = uW2[(8 * j + g) * FS + 8 * k0 + q];
            uint32_t b1 = uW2[(8 * j + g) * FS + 8 * k0 + q + 4];
            mma_tf32(acc[j][0], acc[j][1], acc[j][2], acc[j][3], a0, a1, a2, a3, b0, b1);
        }
    }
    __syncwarp();
    #pragma unroll
    for (int j = 0; j < 8; j++) {
        int cb = j * 8 + 2 * q;
        uX[rA * FS + cb]     = f2tf32(fmaxf(acc[j][0], 0.f));
        uX[rA * FS + cb + 1] = f2tf32(fmaxf(acc[j][1], 0.f));
        uX[rB * FS + cb]     = f2tf32(fmaxf(acc[j][2], 0.f));
        uX[rB * FS + cb + 1] = f2tf32(fmaxf(acc[j][3], 0.f));
    }
    __syncwarp();

    // ---- layer 3 (K = 64, no relu) ----
    #pragma unroll
    for (int j = 0; j < 8; j++) {
        int cb = j * 8 + 2 * q;
        acc[j][0] = acc[j][2] = sB[128 + cb];
        acc[j][1] = acc[j][3] = sB[128 + cb + 1];
    }
    #pragma unroll
    for (int k0 = 0; k0 < 8; k0++) {
        uint32_t a0 = uX[rA * FS + 8 * k0 + q];
        uint32_t a1 = uX[rB * FS + 8 * k0 + q];
        uint32_t a2 = uX[rA * FS + 8 * k0 + q + 4];
        uint32_t a3 = uX[rB * FS + 8 * k0 + q + 4];
        #pragma unroll
        for (int j = 0; j < 8; j++) {
            uint32_t b0 = uW3[(8 * j + g) * FS + 8 * k0 + q];
            uint32_t b1 = uW3[(8 * j + g) * FS + 8 * k0 + q + 4];
            mma_tf32(acc[j][0], acc[j][1], acc[j][2], acc[j][3], a0, a1, a2, a3, b0, b1);
        }
    }
    __syncwarp();

    // ---- epilogue: pack half2 in-place, store 128B rows to binned positions ----
    {
        uint32_t* sH = (uint32_t*)(sm + F_X);
        #pragma unroll
        for (int j = 0; j < 8; j++) {
            int cw = j * 4 + q;
            __half2 hA = __floats2half2_rn(acc[j][0], acc[j][1]);
            __half2 hB = __floats2half2_rn(acc[j][2], acc[j][3]);
            sH[rA * FS + cw] = *(uint32_t*)&hA;
            sH[rB * FS + cw] = *(uint32_t*)&hB;
        }
    }
    __syncthreads();
    {
        const uint32_t* sH = (const uint32_t*)(sm + F_X);
        #pragma unroll
        for (int i = 0; i < 4; i++) {
            int gidx = i * 512 + tid;
            int r = gidx >> 3, c = gidx & 7;
            int dst = sP[r];
            if (dst >= 0)
                ((uint4*)g_wp2)[(size_t)dst * 8 + c] = *(const uint4*)(sH + r * FS + c * 4);
        }
    }
}

// ---------------- persistent fused agg + GRU node update ----------------
// All weights resident in smem; blocks loop over 64-node tiles via atomic queue.
#define P_WIG  0
#define P_WIH  (P_WIG + 64 * FS)          /* 4352  */
#define P_WHH  (P_WIH + 3 * 64 * FS)      /* 17408 */
#define P_BIG  (P_WHH + 3 * 64 * FS)      /* 30464 */
#define P_BIH  (P_BIG + 64)
#define P_BHH  (P_BIH + 192)
#define P_HX32 (P_BHH + 192)              /* 30912 */
#define P_UHX  (P_HX32 + 64 * FS)
#define P_UINP (P_UHX + 64 * FS)
#define P_AGG  (P_UINP + 64 * FS)
#define P_RED  (P_AGG + 64 * FS)          /* 48320 */
#define P_STAT (P_RED + 1024)
#define P_TIL  (P_STAT + 256)             /* 49600 */
#define NODE_FLOATS (P_TIL + 4)
#define NODE_SMEM (NODE_FLOATS * 4)       /* 198416 B */

__global__ __launch_bounds__(512, 1) void node_mma_kernel(
    float* __restrict__ out,
    const float* __restrict__ bih, const float* __restrict__ bhh,
    const float* __restrict__ big, int t, int N)
{
    extern __shared__ float sm[];
    uint32_t* uWig  = (uint32_t*)(sm + P_WIG);
    uint32_t* uWih  = (uint32_t*)(sm + P_WIH);
    uint32_t* uWhh  = (uint32_t*)(sm + P_WHH);
    float*    sBig  = sm + P_BIG;
    float*    sBih  = sm + P_BIH;
    float*    sBhh  = sm + P_BHH;
    float*    sHx32 = sm + P_HX32;
    uint32_t* uHx   = (uint32_t*)(sm + P_UHX);
    uint32_t* uInp  = (uint32_t*)(sm + P_UINP);
    float*    sOut  = sm + P_UINP;
    float*    sAgg  = sm + P_AGG;
    float*    sRed  = sm + P_RED;
    float*    sStat = sm + P_STAT;
    int*      sTil  = (int*)(sm + P_TIL);

    const int tx = threadIdx.x;
    const int wid = tx >> 5, lane = tx & 31;
    const int g = lane >> 2, q = lane & 3;
    const int rowgrp = wid & 3, qt = wid >> 2;
    const int nq = qt * 16;
    const int toff = t * 64;
    const int rA = rowgrp * 16 + g, rB = rA + 8;
    const int ntiles = (N + 63) / 64;

    // ---- stage ALL weights + biases once ----
    for (int idx = tx; idx < 4096; idx += 512) {
        int o = idx >> 6, k = idx & 63;
        uWig[o * FS + k] = g_wigu[idx];
    }
    for (int idx = tx; idx < 12288; idx += 512) {
        int c = idx >> 12, r = idx & 4095;
        int o = r >> 6, k = r & 63;
        uWih[c * 4352 + o * FS + k] = g_wihu[idx];
        uWhh[c * 4352 + o * FS + k] = g_whhu[idx];
    }
    if (tx < 64)  sBig[tx] = big[tx];
    if (tx < 192) { sBih[tx] = bih[tx]; sBhh[tx] = bhh[tx]; }

    for (;;) {
        if (tx == 0) sTil[0] = atomicAdd(&g_tilq[t], 1);
        __syncthreads();   // broadcast tile; also orders prior tile's sOut reads vs new staging
        const int tile = sTil[0];
        if (tile >= ntiles) break;
        const int n0 = tile * 64;
        const int gnA = n0 + rA, gnB = n0 + rB;

        // ---- stage hx ----
        for (int idx = tx; idx < 4096; idx += 512) {
            int n = idx >> 6, k = idx & 63;
            float v = (n0 + n < N) ? out[(size_t)(n0 + n) * 256 + toff + k] : 0.f;
            sHx32[n * FS + k] = v;
            uHx[n * FS + k] = f2tf32(v);
        }

        // ---- in-block aggregation: warp wid owns nodes wid*4 .. wid*4+3 ----
        {
            const float* o_t = out + toff;
            const __half2* w2 = (const __half2*)g_wp2;
            #pragma unroll
            for (int u = 0; u < 4; u++) {
                int ln = wid * 4 + u;
                int gn = n0 + ln;
                float ax = 0.f, ay = 0.f, bx = 0.f, by = 0.f;
                if (gn < N) {
                    int start = g_start[gn];
                    int deg   = g_degi[gn];
                    int i = 0;
                    for (; i + 2 <= deg; i += 2) {
                        int p0 = start + i, p1 = start + i + 1;
                        int s0 = g_srcp[p0], s1 = g_srcp[p1];
                        float2 w0 = __half22float2(w2[(size_t)p0 * 32 + lane]);
                        float2 h0 = *(const float2*)(o_t + (size_t)s0 * 256 + 2 * lane);
                        float2 w1 = __half22float2(w2[(size_t)p1 * 32 + lane]);
                        float2 h1 = *(const float2*)(o_t + (size_t)s1 * 256 + 2 * lane);
                        ax += w0.x * h0.x; ay += w0.y * h0.y;
                        bx += w1.x * h1.x; by += w1.y * h1.y;
                    }
                    if (i < deg) {
                        int p0 = start + i;
                        int s0 = g_srcp[p0];
                        float2 w0 = __half22float2(w2[(size_t)p0 * 32 + lane]);
                        float2 h0 = *(const float2*)(o_t + (size_t)s0 * 256 + 2 * lane);
                        ax += w0.x * h0.x; ay += w0.y * h0.y;
                    }
                }
                sAgg[ln * FS + 2 * lane]     = ax + bx;
                sAgg[ln * FS + 2 * lane + 1] = ay + by;
            }
        }
        __syncthreads();

        // ---- inp = sigmoid(hx @ Wig^T + big) * agg * invdeg ----
        {
            float aw[2][4];
            #pragma unroll
            for (int j = 0; j < 2; j++) {
                int cb = nq + 8 * j + 2 * q;
                aw[j][0] = aw[j][2] = sBig[cb];
                aw[j][1] = aw[j][3] = sBig[cb + 1];
            }
            #pragma unroll
            for (int k0 = 0; k0 < 8; k0++) {
                uint32_t a0 = uHx[rA * FS + 8 * k0 + q];
                uint32_t a1 = uHx[rB * FS + 8 * k0 + q];
                uint32_t a2 = uHx[rA * FS + 8 * k0 + q + 4];
                uint32_t a3 = uHx[rB * FS + 8 * k0 + q + 4];
                #pragma unroll
                for (int j = 0; j < 2; j++) {
                    uint32_t b0 = uWig[(nq + 8 * j + g) * FS + 8 * k0 + q];
                    uint32_t b1 = uWig[(nq + 8 * j + g) * FS + 8 * k0 + q + 4];
                    mma_tf32(aw[j][0], aw[j][1], aw[j][2], aw[j][3], a0, a1, a2, a3, b0, b1);
                }
            }
            float invA = (gnA < N) ? 1.f / fmaxf((float)g_degi[gnA], 1.f) : 0.f;
            float invB = (gnB < N) ? 1.f / fmaxf((float)g_degi[gnB], 1.f) : 0.f;
            #pragma unroll
            for (int j = 0; j < 2; j++) {
                int cb = nq + 8 * j + 2 * q;
                uInp[rA * FS + cb]     = f2tf32(sigm(aw[j][0]) * sAgg[rA * FS + cb]     * invA);
                uInp[rA * FS + cb + 1] = f2tf32(sigm(aw[j][1]) * sAgg[rA * FS + cb + 1] * invA);
                uInp[rB * FS + cb]     = f2tf32(sigm(aw[j][2]) * sAgg[rB * FS + cb]     * invB);
                uInp[rB * FS + cb + 1] = f2tf32(sigm(aw[j][3]) * sAgg[rB * FS + cb + 1] * invB);
            }
        }
        __syncthreads();

        // ---- GI = inp @ Wih^T ; GH = hx @ Whh^T : resident weights, no staging ----
        float accI[3][2][4], accH[3][2][4];
        #pragma unroll
        for (int c = 0; c < 3; c++) {
            #pragma unroll
            for (int j = 0; j < 2; j++)
                #pragma unroll
                for (int v = 0; v < 4; v++) { accI[c][j][v] = 0.f; accH[c][j][v] = 0.f; }
            #pragma unroll
            for (int k0 = 0; k0 < 8; k0++) {
                uint32_t aI0 = uInp[rA * FS + 8 * k0 + q];
                uint32_t aI1 = uInp[rB * FS + 8 * k0 + q];
                uint32_t aI2 = uInp[rA * FS + 8 * k0 + q + 4];
                uint32_t aI3 = uInp[rB * FS + 8 * k0 + q + 4];
                uint32_t aH0 = uHx[rA * FS + 8 * k0 + q];
                uint32_t aH1 = uHx[rB * FS + 8 * k0 + q];
                uint32_t aH2 = uHx[rA * FS + 8 * k0 + q + 4];
                uint32_t aH3 = uHx[rB * FS + 8 * k0 + q + 4];
                #pragma unroll
                for (int j = 0; j < 2; j++) {
                    int brow = c * 4352 + (nq + 8 * j + g) * FS + 8 * k0 + q;
                    uint32_t b0 = uWih[brow], b1 = uWih[brow + 4];
                    mma_tf32(accI[c][j][0], accI[c][j][1], accI[c][j][2], accI[c][j][3],
                             aI0, aI1, aI2, aI3, b0, b1);
                    uint32_t c0 = uWhh[brow], c1 = uWhh[brow + 4];
                    mma_tf32(accH[c][j][0], accH[c][j][1], accH[c][j][2], accH[c][j][3],
                             aH0, aH1, aH2, aH3, c0, c1);
                }
            }
        }

        // ---- instance-norm stats ----
        {
            float sIA = 0.f, qIA = 0.f, sIB = 0.f, qIB = 0.f;
            float sHA = 0.f, qHA = 0.f, sHB = 0.f, qHB = 0.f;
            #pragma unroll
            for (int c = 0; c < 3; c++)
                #pragma unroll
                for (int j = 0; j < 2; j++) {
                    float a0 = accI[c][j][0], a1 = accI[c][j][1];
                    float a2 = accI[c][j][2], a3 = accI[c][j][3];
                    sIA += a0 + a1; qIA += a0 * a0 + a1 * a1;
                    sIB += a2 + a3; qIB += a2 * a2 + a3 * a3;
                    float h0 = accH[c][j][0], h1 = accH[c][j][1];
                    float h2 = accH[c][j][2], h3 = accH[c][j][3];
                    sHA += h0 + h1; qHA += h0 * h0 + h1 * h1;
                    sHB += h2 + h3; qHB += h2 * h2 + h3 * h3;
                }
            #pragma unroll
            for (int m = 1; m <= 2; m <<= 1) {
                sIA += __shfl_xor_sync(0xffffffffu, sIA, m);
                qIA += __shfl_xor_sync(0xffffffffu, qIA, m);
                sIB += __shfl_xor_sync(0xffffffffu, sIB, m);
                qIB += __shfl_xor_sync(0xffffffffu, qIB, m);
                sHA += __shfl_xor_sync(0xffffffffu, sHA, m);
                qHA += __shfl_xor_sync(0xffffffffu, qHA, m);
                sHB += __shfl_xor_sync(0xffffffffu, sHB, m);
                qHB += __shfl_xor_sync(0xffffffffu, qHB, m);
            }
            if (q == 0) {
                float* rdA = sRed + (qt * 64 + rA) * 4;
                rdA[0] = sIA; rdA[1] = qIA; rdA[2] = sHA; rdA[3] = qHA;
                float* rdB = sRed + (qt * 64 + rB) * 4;
                rdB[0] = sIB; rdB[1] = qIB; rdB[2] = sHB; rdB[3] = qHB;
            }
        }
        __syncthreads();
        if (tx < 64) {
            float sI = 0.f, qI = 0.f, sH = 0.f, qH = 0.f;
            #pragma unroll
            for (int qt2 = 0; qt2 < 4; qt2++) {
                const float* rd = sRed + (qt2 * 64 + tx) * 4;
                sI += rd[0]; qI += rd[1]; sH += rd[2]; qH += rd[3];
            }
            float muI = sI * (1.f / 192.f);
            float varI = qI * (1.f / 192.f) - muI * muI;
            float muH = sH * (1.f / 192.f);
            float varH = qH * (1.f / 192.f) - muH * muH;
            sStat[tx * 4 + 0] = muI;
            sStat[tx * 4 + 1] = rsqrtf(varI + 1e-5f);
            sStat[tx * 4 + 2] = muH;
            sStat[tx * 4 + 3] = rsqrtf(varH + 1e-5f);
        }
        __syncthreads();

        // ---- gates + stage result (overwrites uInp region) ----
        {
            float muIA = sStat[rA * 4 + 0], rsIA = sStat[rA * 4 + 1];
            float muHA = sStat[rA * 4 + 2], rsHA = sStat[rA * 4 + 3];
            float muIB = sStat[rB * 4 + 0], rsIB = sStat[rB * 4 + 1];
            float muHB = sStat[rB * 4 + 2], rsHB = sStat[rB * 4 + 3];
            #pragma unroll
            for (int j = 0; j < 2; j++) {
                #pragma unroll
                for (int v = 0; v < 2; v++) {
                    int cb = nq + 8 * j + 2 * q + v;
                    float b_r = sBih[cb],       c_r = sBhh[cb];
                    float b_i = sBih[64 + cb],  c_i = sBhh[64 + cb];
                    float b_n = sBih[128 + cb], c_n = sBhh[128 + cb];
                    {
                        float i_r = (accI[0][j][v] - muIA) * rsIA;
                        float i_i = (accI[1][j][v] - muIA) * rsIA;
                        float i_n = (accI[2][j][v] - muIA) * rsIA;
                        float h_r = (accH[0][j][v] - muHA) * rsHA;
                        float h_i = (accH[1][j][v] - muHA) * rsHA;
                        float h_n = (accH[2][j][v] - muHA) * rsHA;
                        float r  = sigm(i_r + b_r + h_r + c_r);
                        float z  = sigm(i_i + b_i + h_i + c_i);
                        float ng = tanhf(i_n + b_n + r * (h_n + c_n));
                        float hxo = sHx32[rA * FS + cb];
                        sOut[rA * FS + cb] = ng + z * (hxo - ng);
                    }
                    {
                        float i_r = (accI[0][j][v + 2] - muIB) * rsIB;
                        float i_i = (accI[1][j][v + 2] - muIB) * rsIB;
                        float i_n = (accI[2][j][v + 2] - muIB) * rsIB;
                        float h_r = (accH[0][j][v + 2] - muHB) * rsHB;
                        float h_i = (accH[1][j][v + 2] - muHB) * rsHB;
                        float h_n = (accH[2][j][v + 2] - muHB) * rsHB;
                        float r  = sigm(i_r + b_r + h_r + c_r);
                        float z  = sigm(i_i + b_i + h_i + c_i);
                        float ng = tanhf(i_n + b_n + r * (h_n + c_n));
                        float hxo = sHx32[rB * FS + cb];
                        sOut[rB * FS + cb] = ng + z * (hxo - ng);
                    }
                }
            }
        }
        __syncthreads();

        // ---- coalesced write of new hx ----
        for (int idx = tx; idx < 4096; idx += 512) {
            int n = idx >> 6, k = idx & 63;
            if (n0 + n < N)
                out[(size_t)(n0 + n) * 256 + toff + 64 + k] = sOut[n * FS + k];
        }
        // loop-top __syncthreads orders these reads vs next tile's staging
    }
}

// ---------------- launcher ----------------
extern "C" void kernel_launch(void* const* d_in, const int* in_sizes, int n_in,
                              void* d_out, int out_size)
{
    const float* hx  = (const float*)d_in[0];
    const void*  eix = d_in[1];
    const float* ef  = (const float*)d_in[2];
    const float* fW1 = (const float*)d_in[3];
    const float* fb1 = (const float*)d_in[4];
    const float* fW2 = (const float*)d_in[5];
    const float* fb2 = (const float*)d_in[6];
    const float* fW3 = (const float*)d_in[7];
    const float* fb3 = (const float*)d_in[8];
    const float* Wih = (const float*)d_in[9];
    const float* Whh = (const float*)d_in[10];
    const float* bih = (const float*)d_in[11];
    const float* bhh = (const float*)d_in[12];
    const float* Wig = (const float*)d_in[13];
    const float* big = (const float*)d_in[14];
    float* out = (float*)d_out;

    const int N = in_sizes[0] / 64;
    const int E = in_sizes[2] / 13;
    const int nb = (N + 1023) / 1024;

    cudaFuncSetAttribute(fnet_mma_kernel, cudaFuncAttributeMaxDynamicSharedMemorySize, FNET_SMEM);
    cudaFuncSetAttribute(node_mma_kernel, cudaFuncAttributeMaxDynamicSharedMemorySize, NODE_SMEM);

    detect_kernel<<<1, 256>>>((const int*)eix);
    prep_kernel<<<(12288 + 255) / 256, 256>>>(fW1, fW2, fW3, Wig, Wih, Whh);
    copy_hx_kernel<<<(N * 64 + 255) / 256, 256>>>(hx, out, N);
    zero_cnt_kernel<<<(N + 255) / 256, 256>>>(N);
    degi_kernel<<<(E + 255) / 256, 256>>>(eix, E);
    scan1_kernel<<<nb, 256>>>(N);
    scan2_kernel<<<1, 32>>>(nb);
    scan3_kernel<<<(N + 255) / 256, 256>>>(N);
    bin_kernel<<<(E + 255) / 256, 256>>>(eix, E);
    fnet_mma_kernel<<<(E + 255) / 256, 512, FNET_SMEM>>>(ef, fb1, fb2, fb3, E);

    for (int t = 0; t < 3; t++)
        node_mma_kernel<<<148, 512, NODE_SMEM>>>(out, bih, bhh, big, t, N);
}

// round 13
// speedup vs baseline: 1.3644x; 1.1256x over previous
#include <cuda_runtime.h>
#include <cuda_fp16.h>
#include <cstdint>

#define NN 100000
#define NE 1250000
#define FS 68

// ---------------- device scratch (no allocs allowed) ----------------
__device__ __align__(16) uint32_t g_wp2[(size_t)NE * 32]; // per-edge weights as half2, BINNED by dst
__device__ int g_srcp[NE];                               // src node per binned position
__device__ int g_invperm[NE];                            // edge -> binned position
__device__ int g_degi[NN];
__device__ int g_start[NN];
__device__ int g_cursor[NN];
__device__ int g_bsum[128];
__device__ int g_tilq[4];                                // persistent-kernel tile queues
__device__ int g_idx64;

// pre-converted tf32 weights
__device__ uint32_t g_fw1u[1024];    // [64][16] padded
__device__ uint32_t g_fw2u[4096];
__device__ uint32_t g_fw3u[4096];
__device__ uint32_t g_wigu[4096];
__device__ uint32_t g_wihu[12288];
__device__ uint32_t g_whhu[12288];

__device__ __forceinline__ float sigm(float x) { return 1.f / (1.f + expf(-x)); }

__device__ __forceinline__ uint32_t f2tf32(float x) {
    uint32_t u;
    asm("cvt.rna.tf32.f32 %0, %1;" : "=r"(u) : "f"(x));
    return u;
}

// D[m][n] = sum_k A[m][k] * W[n][k], m16n8k8 tf32
__device__ __forceinline__ void mma_tf32(float& c0, float& c1, float& c2, float& c3,
                                         uint32_t a0, uint32_t a1, uint32_t a2, uint32_t a3,
                                         uint32_t b0, uint32_t b1)
{
    asm volatile("mma.sync.aligned.m16n8k8.row.col.f32.tf32.tf32.f32 "
                 "{%0,%1,%2,%3}, {%4,%5,%6,%7}, {%8,%9}, {%0,%1,%2,%3};"
                 : "+f"(c0), "+f"(c1), "+f"(c2), "+f"(c3)
                 : "r"(a0), "r"(a1), "r"(a2), "r"(a3), "r"(b0), "r"(b1));
}

// ---------------- launch 1: prep (+ edge_index dtype detect in block 0) ----------------
__global__ void prep_kernel(const float* __restrict__ fW1, const float* __restrict__ fW2,
                            const float* __restrict__ fW3, const float* __restrict__ Wig,
                            const float* __restrict__ Wih, const float* __restrict__ Whh,
                            const int* __restrict__ eidx_raw)
{
    int i = blockIdx.x * blockDim.x + threadIdx.x;
    if (blockIdx.x == 0) {
        __shared__ int nz;
        if (threadIdx.x == 0) nz = 0;
        __syncthreads();
        if (eidx_raw[2 * threadIdx.x + 1] != 0) atomicOr(&nz, 1);
        __syncthreads();
        if (threadIdx.x == 0) g_idx64 = (nz == 0) ? 1 : 0;
    }
    if (i < 1024) {
        int o = i >> 4, k = i & 15;
        g_fw1u[i] = (k < 13) ? f2tf32(fW1[o * 13 + k]) : 0u;
    }
    if (i < 4096) {
        g_fw2u[i] = f2tf32(fW2[i]);
        g_fw3u[i] = f2tf32(fW3[i]);
        g_wigu[i] = f2tf32(Wig[i]);
    }
    if (i < 12288) {
        g_wihu[i] = f2tf32(Wih[i]);
        g_whhu[i] = f2tf32(Whh[i]);
    }
}

// ---------------- launch 2: copy hx + zero counters/queues ----------------
__global__ void copy_hx_kernel(const float* __restrict__ hx, float* __restrict__ out, int N) {
    int idx = blockIdx.x * blockDim.x + threadIdx.x;
    if (idx < N) { g_degi[idx] = 0; g_cursor[idx] = 0; }
    if (idx < 4) g_tilq[idx] = 0;
    if (idx < N * 64) {
        int n = idx >> 6, k = idx & 63;
        out[(size_t)n * 256 + k] = hx[idx];
    }
}

// ---------------- launch 3: degree count ----------------
__global__ void degi_kernel(const void* __restrict__ eidx, int E) {
    int e = blockIdx.x * blockDim.x + threadIdx.x;
    if (e >= E) return;
    int d;
    if (g_idx64) d = (int)((const long long*)eidx)[e];
    else         d = ((const int*)eidx)[e];
    atomicAdd(&g_degi[d], 1);
}

// ---------------- launch 4: per-1024-element block scan ----------------
__global__ void scan1_kernel(int N) {
    __shared__ int sS[256];
    int b = blockIdx.x, tid = threadIdx.x;
    int base = b * 1024 + tid * 4;
    int v0 = (base + 0 < N) ? g_degi[base + 0] : 0;
    int v1 = (base + 1 < N) ? g_degi[base + 1] : 0;
    int v2 = (base + 2 < N) ? g_degi[base + 2] : 0;
    int v3 = (base + 3 < N) ? g_degi[base + 3] : 0;
    int tsum = v0 + v1 + v2 + v3;
    sS[tid] = tsum;
    __syncthreads();
    for (int off = 1; off < 256; off <<= 1) {
        int x = (tid >= off) ? sS[tid - off] : 0;
        __syncthreads();
        sS[tid] += x;
        __syncthreads();
    }
    int excl = sS[tid] - tsum;
    if (base + 0 < N) g_start[base + 0] = excl;
    if (base + 1 < N) g_start[base + 1] = excl + v0;
    if (base + 2 < N) g_start[base + 2] = excl + v0 + v1;
    if (base + 3 < N) g_start[base + 3] = excl + v0 + v1 + v2;
    if (tid == 255) g_bsum[b] = sS[255];
}

// ---------------- launch 5: add cross-block prefix (inline) ----------------
__global__ void scan3_kernel(int N) {
    __shared__ int soff;
    int b = blockIdx.x;
    int grp = b >> 2;            // this 256-thread block lies in one 1024-group
    if (threadIdx.x < 32) {
        int acc = 0;
        for (int j = threadIdx.x; j < grp; j += 32) acc += g_bsum[j];
        #pragma unroll
        for (int m = 16; m; m >>= 1) acc += __shfl_xor_sync(0xffffffffu, acc, m);
        if (threadIdx.x == 0) soff = acc;
    }
    __syncthreads();
    int i = b * 256 + threadIdx.x;
    if (i < N) g_start[i] += soff;
}

// ---------------- launch 6: bin edges by destination ----------------
__global__ void bin_kernel(const void* __restrict__ eidx, int E) {
    int e = blockIdx.x * blockDim.x + threadIdx.x;
    if (e >= E) return;
    int d, s;
    if (g_idx64) {
        const long long* p = (const long long*)eidx;
        d = (int)p[e]; s = (int)p[E + e];
    } else {
        const int* p = (const int*)eidx;
        d = p[e]; s = p[E + e];
    }
    int pos = g_start[d] + atomicAdd(&g_cursor[d], 1);
    g_invperm[e] = pos;
    g_srcp[pos] = s;
}

// ---------------- launch 7: PERSISTENT fnet via mma.sync tf32 ----------------
// grid=148; weights staged once per block, then stride over 256-edge tiles.
#define F_X   0
#define F_W1  (256 * FS)
#define F_W2  (F_W1 + 64 * FS)
#define F_W3  (F_W2 + 64 * FS)
#define F_B   (F_W3 + 64 * FS)
#define F_P   (F_B + 192)
#define FNET_FLOATS (F_P + 256)
#define FNET_SMEM (FNET_FLOATS * 4)

__global__ __launch_bounds__(512, 1) void fnet_mma_kernel(
    const float* __restrict__ ef,
    const float* __restrict__ fb1, const float* __restrict__ fb2,
    const float* __restrict__ fb3, int E)
{
    extern __shared__ float sm[];
    uint32_t* uX  = (uint32_t*)(sm + F_X);
    uint32_t* uW1 = (uint32_t*)(sm + F_W1);
    uint32_t* uW2 = (uint32_t*)(sm + F_W2);
    uint32_t* uW3 = (uint32_t*)(sm + F_W3);
    float*    sB  = sm + F_B;
    int*      sP  = (int*)(sm + F_P);

    const int tid = threadIdx.x;
    const int wid = tid >> 5, lane = tid & 31;
    const int g = lane >> 2, q = lane & 3;
    const int r0 = wid * 16;
    const int rA = r0 + g, rB = r0 + 8 + g;
    const int ntiles = (E + 255) / 256;

    // ---- stage weights + biases ONCE ----
    for (int idx = tid; idx < 1024; idx += 512) {
        int o = idx >> 4, k = idx & 15;
        uW1[o * FS + k] = g_fw1u[idx];
    }
    for (int idx = tid; idx < 4096; idx += 512) {
        int o = idx >> 6, k = idx & 63;
        uW2[o * FS + k] = g_fw2u[idx];
        uW3[o * FS + k] = g_fw3u[idx];
    }
    if (tid < 64) { sB[tid] = fb1[tid]; sB[64 + tid] = fb2[tid]; sB[128 + tid] = fb3[tid]; }

    for (int tile = blockIdx.x; tile < ntiles; tile += 148) {
        const int e0 = tile * 256;

        // ---- stage X (K padded to 16, tf32) + perm ----
        for (int idx = tid; idx < 256 * 16; idx += 512) {
            int e = idx >> 4, k = idx & 15;
            float v = (k < 13 && e0 + e < E) ? ef[(size_t)(e0 + e) * 13 + k] : 0.f;
            uX[e * FS + k] = f2tf32(v);
        }
        if (tid < 256) sP[tid] = (e0 + tid < E) ? g_invperm[e0 + tid] : -1;
        __syncthreads();

        float acc[8][4];

        // ---- layer 1 (K = 16) ----
        #pragma unroll
        for (int j = 0; j < 8; j++) {
            int cb = j * 8 + 2 * q;
            acc[j][0] = acc[j][2] = sB[cb];
            acc[j][1] = acc[j][3] = sB[cb + 1];
        }
        #pragma unroll
        for (int k0 = 0; k0 < 2; k0++) {
            uint32_t a0 = uX[rA * FS + 8 * k0 + q];
            uint32_t a1 = uX[rB * FS + 8 * k0 + q];
            uint32_t a2 = uX[rA * FS + 8 * k0 + q + 4];
            uint32_t a3 = uX[rB * FS + 8 * k0 + q + 4];
            #pragma unroll
            for (int j = 0; j < 8; j++) {
                uint32_t b0 = uW1[(8 * j + g) * FS + 8 * k0 + q];
                uint32_t b1 = uW1[(8 * j + g) * FS + 8 * k0 + q + 4];
                mma_tf32(acc[j][0], acc[j][1], acc[j][2], acc[j][3], a0, a1, a2, a3, b0, b1);
            }
        }
        #pragma unroll
        for (int j = 0; j < 8; j++) {
            int cb = j * 8 + 2 * q;
            uX[rA * FS + cb]     = f2tf32(fmaxf(acc[j][0], 0.f));
            uX[rA * FS + cb + 1] = f2tf32(fmaxf(acc[j][1], 0.f));
            uX[rB * FS + cb]     = f2tf32(fmaxf(acc[j][2], 0.f));
            uX[rB * FS + cb + 1] = f2tf32(fmaxf(acc[j][3], 0.f));
        }
        __syncwarp();

        // ---- layer 2 (K = 64, relu) ----
        #pragma unroll
        for (int j = 0; j < 8; j++) {
            int cb = j * 8 + 2 * q;
            acc[j][0] = acc[j][2] = sB[64 + cb];
            acc[j][1] = acc[j][3] = sB[64 + cb + 1];
        }
        #pragma unroll
        for (int k0 = 0; k0 < 8; k0++) {
            uint32_t a0 = uX[rA * FS + 8 * k0 + q];
            uint32_t a1 = uX[rB * FS + 8 * k0 + q];
            uint32_t a2 = uX[rA * FS + 8 * k0 + q + 4];
            uint32_t a3 = uX[rB * FS + 8 * k0 + q + 4];
            #pragma unroll
            for (int j = 0; j < 8; j++) {
                uint32_t b0 = uW2[(8 * j + g) * FS + 8 * k0 + q];
                uint32_t b1 = uW2[(8 * j + g) * FS + 8 * k0 + q + 4];
                mma_tf32(acc[j][0], acc[j][1], acc[j][2], acc[j][3], a0, a1, a2, a3, b0, b1);
            }
        }
        __syncwarp();
        #pragma unroll
        for (int j = 0; j < 8; j++) {
            int cb = j * 8 + 2 * q;
            uX[rA * FS + cb]     = f2tf32(fmaxf(acc[j][0], 0.f));
            uX[rA * FS + cb + 1] = f2tf32(fmaxf(acc[j][1], 0.f));
            uX[rB * FS + cb]     = f2tf32(fmaxf(acc[j][2], 0.f));
            uX[rB * FS + cb + 1] = f2tf32(fmaxf(acc[j][3], 0.f));
        }
        __syncwarp();

        // ---- layer 3 (K = 64, no relu) ----
        #pragma unroll
        for (int j = 0; j < 8; j++) {
            int cb = j * 8 + 2 * q;
            acc[j][0] = acc[j][2] = sB[128 + cb];
            acc[j][1] = acc[j][3] = sB[128 + cb + 1];
        }
        #pragma unroll
        for (int k0 = 0; k0 < 8; k0++) {
            uint32_t a0 = uX[rA * FS + 8 * k0 + q];
            uint32_t a1 = uX[rB * FS + 8 * k0 + q];
            uint32_t a2 = uX[rA * FS + 8 * k0 + q + 4];
            uint32_t a3 = uX[rB * FS + 8 * k0 + q + 4];
            #pragma unroll
            for (int j = 0; j < 8; j++) {
                uint32_t b0 = uW3[(8 * j + g) * FS + 8 * k0 + q];
                uint32_t b1 = uW3[(8 * j + g) * FS + 8 * k0 + q + 4];
                mma_tf32(acc[j][0], acc[j][1], acc[j][2], acc[j][3], a0, a1, a2, a3, b0, b1);
            }
        }
        __syncwarp();

        // ---- epilogue: pack half2 in-place, store 128B rows to binned positions ----
        {
            uint32_t* sH = (uint32_t*)(sm + F_X);
            #pragma unroll
            for (int j = 0; j < 8; j++) {
                int cw = j * 4 + q;
                __half2 hA = __floats2half2_rn(acc[j][0], acc[j][1]);
                __half2 hB = __floats2half2_rn(acc[j][2], acc[j][3]);
                sH[rA * FS + cw] = *(uint32_t*)&hA;
                sH[rB * FS + cw] = *(uint32_t*)&hB;
            }
        }
        __syncthreads();
        {
            const uint32_t* sH = (const uint32_t*)(sm + F_X);
            #pragma unroll
            for (int i = 0; i < 4; i++) {
                int gidx = i * 512 + tid;
                int r = gidx >> 3, c = gidx & 7;
                int dst = sP[r];
                if (dst >= 0)
                    ((uint4*)g_wp2)[(size_t)dst * 8 + c] = *(const uint4*)(sH + r * FS + c * 4);
            }
        }
        __syncthreads();   // all stores done before next tile overwrites uX
    }
}

// ---------------- launches 8-10: persistent fused agg + GRU node update ----------------
#define P_WIG  0
#define P_WIH  (P_WIG + 64 * FS)          /* 4352  */
#define P_WHH  (P_WIH + 3 * 64 * FS)      /* 17408 */
#define P_BIG  (P_WHH + 3 * 64 * FS)      /* 30464 */
#define P_BIH  (P_BIG + 64)
#define P_BHH  (P_BIH + 192)
#define P_HX32 (P_BHH + 192)              /* 30912 */
#define P_UHX  (P_HX32 + 64 * FS)
#define P_UINP (P_UHX + 64 * FS)
#define P_AGG  (P_UINP + 64 * FS)
#define P_RED  (P_AGG + 64 * FS)          /* 48320 */
#define P_STAT (P_RED + 1024)
#define P_TIL  (P_STAT + 256)             /* 49600 */
#define NODE_FLOATS (P_TIL + 4)
#define NODE_SMEM (NODE_FLOATS * 4)       /* 198416 B */

__global__ __launch_bounds__(512, 1) void node_mma_kernel(
    float* __restrict__ out,
    const float* __restrict__ bih, const float* __restrict__ bhh,
    const float* __restrict__ big, int t, int N)
{
    extern __shared__ float sm[];
    uint32_t* uWig  = (uint32_t*)(sm + P_WIG);
    uint32_t* uWih  = (uint32_t*)(sm + P_WIH);
    uint32_t* uWhh  = (uint32_t*)(sm + P_WHH);
    float*    sBig  = sm + P_BIG;
    float*    sBih  = sm + P_BIH;
    float*    sBhh  = sm + P_BHH;
    float*    sHx32 = sm + P_HX32;
    uint32_t* uHx   = (uint32_t*)(sm + P_UHX);
    uint32_t* uInp  = (uint32_t*)(sm + P_UINP);
    float*    sOut  = sm + P_UINP;
    float*    sAgg  = sm + P_AGG;
    float*    sRed  = sm + P_RED;
    float*    sStat = sm + P_STAT;
    int*      sTil  = (int*)(sm + P_TIL);

    const int tx = threadIdx.x;
    const int wid = tx >> 5, lane = tx & 31;
    const int g = lane >> 2, q = lane & 3;
    const int rowgrp = wid & 3, qt = wid >> 2;
    const int nq = qt * 16;
    const int toff = t * 64;
    const int rA = rowgrp * 16 + g, rB = rA + 8;
    const int ntiles = (N + 63) / 64;

    // ---- stage ALL weights + biases once ----
    for (int idx = tx; idx < 4096; idx += 512) {
        int o = idx >> 6, k = idx & 63;
        uWig[o * FS + k] = g_wigu[idx];
    }
    for (int idx = tx; idx < 12288; idx += 512) {
        int c = idx >> 12, r = idx & 4095;
        int o = r >> 6, k = r & 63;
        uWih[c * 4352 + o * FS + k] = g_wihu[idx];
        uWhh[c * 4352 + o * FS + k] = g_whhu[idx];
    }
    if (tx < 64)  sBig[tx] = big[tx];
    if (tx < 192) { sBih[tx] = bih[tx]; sBhh[tx] = bhh[tx]; }

    for (;;) {
        if (tx == 0) sTil[0] = atomicAdd(&g_tilq[t], 1);
        __syncthreads();
        const int tile = sTil[0];
        if (tile >= ntiles) break;
        const int n0 = tile * 64;
        const int gnA = n0 + rA, gnB = n0 + rB;

        // ---- stage hx ----
        for (int idx = tx; idx < 4096; idx += 512) {
            int n = idx >> 6, k = idx & 63;
            float v = (n0 + n < N) ? out[(size_t)(n0 + n) * 256 + toff + k] : 0.f;
            sHx32[n * FS + k] = v;
            uHx[n * FS + k] = f2tf32(v);
        }

        // ---- in-block aggregation: warp wid owns nodes wid*4 .. wid*4+3 ----
        {
            const float* o_t = out + toff;
            const __half2* w2 = (const __half2*)g_wp2;
            #pragma unroll
            for (int u = 0; u < 4; u++) {
                int ln = wid * 4 + u;
                int gn = n0 + ln;
                float ax = 0.f, ay = 0.f, bx = 0.f, by = 0.f;
                if (gn < N) {
                    int start = g_start[gn];
                    int deg   = g_degi[gn];
                    int i = 0;
                    for (; i + 2 <= deg; i += 2) {
                        int p0 = start + i, p1 = start + i + 1;
                        int s0 = g_srcp[p0], s1 = g_srcp[p1];
                        float2 w0 = __half22float2(w2[(size_t)p0 * 32 + lane]);
                        float2 h0 = *(const float2*)(o_t + (size_t)s0 * 256 + 2 * lane);
                        float2 w1 = __half22float2(w2[(size_t)p1 * 32 + lane]);
                        float2 h1 = *(const float2*)(o_t + (size_t)s1 * 256 + 2 * lane);
                        ax += w0.x * h0.x; ay += w0.y * h0.y;
                        bx += w1.x * h1.x; by += w1.y * h1.y;
                    }
                    if (i < deg) {
                        int p0 = start + i;
                        int s0 = g_srcp[p0];
                        float2 w0 = __half22float2(w2[(size_t)p0 * 32 + lane]);
                        float2 h0 = *(const float2*)(o_t + (size_t)s0 * 256 + 2 * lane);
                        ax += w0.x * h0.x; ay += w0.y * h0.y;
                    }
                }
                sAgg[ln * FS + 2 * lane]     = ax + bx;
                sAgg[ln * FS + 2 * lane + 1] = ay + by;
            }
        }
        __syncthreads();

        // ---- inp = sigmoid(hx @ Wig^T + big) * agg * invdeg ----
        {
            float aw[2][4];
            #pragma unroll
            for (int j = 0; j < 2; j++) {
                int cb = nq + 8 * j + 2 * q;
                aw[j][0] = aw[j][2] = sBig[cb];
                aw[j][1] = aw[j][3] = sBig[cb + 1];
            }
            #pragma unroll
            for (int k0 = 0; k0 < 8; k0++) {
                uint32_t a0 = uHx[rA * FS + 8 * k0 + q];
                uint32_t a1 = uHx[rB * FS + 8 * k0 + q];
                uint32_t a2 = uHx[rA * FS + 8 * k0 + q + 4];
                uint32_t a3 = uHx[rB * FS + 8 * k0 + q + 4];
                #pragma unroll
                for (int j = 0; j < 2; j++) {
                    uint32_t b0 = uWig[(nq + 8 * j + g) * FS + 8 * k0 + q];
                    uint32_t b1 = uWig[(nq + 8 * j + g) * FS + 8 * k0 + q + 4];
                    mma_tf32(aw[j][0], aw[j][1], aw[j][2], aw[j][3], a0, a1, a2, a3, b0, b1);
                }
            }
            float invA = (gnA < N) ? 1.f / fmaxf((float)g_degi[gnA], 1.f) : 0.f;
            float invB = (gnB < N) ? 1.f / fmaxf((float)g_degi[gnB], 1.f) : 0.f;
            #pragma unroll
            for (int j = 0; j < 2; j++) {
                int cb = nq + 8 * j + 2 * q;
                uInp[rA * FS + cb]     = f2tf32(sigm(aw[j][0]) * sAgg[rA * FS + cb]     * invA);
                uInp[rA * FS + cb + 1] = f2tf32(sigm(aw[j][1]) * sAgg[rA * FS + cb + 1] * invA);
                uInp[rB * FS + cb]     = f2tf32(sigm(aw[j][2]) * sAgg[rB * FS + cb]     * invB);
                uInp[rB * FS + cb + 1] = f2tf32(sigm(aw[j][3]) * sAgg[rB * FS + cb + 1] * invB);
            }
        }
        __syncthreads();

        // ---- GI = inp @ Wih^T ; GH = hx @ Whh^T : resident weights ----
        float accI[3][2][4], accH[3][2][4];
        #pragma unroll
        for (int c = 0; c < 3; c++) {
            #pragma unroll
            for (int j = 0; j < 2; j++)
                #pragma unroll
                for (int v = 0; v < 4; v++) { accI[c][j][v] = 0.f; accH[c][j][v] = 0.f; }
            #pragma unroll
            for (int k0 = 0; k0 < 8; k0++) {
                uint32_t aI0 = uInp[rA * FS + 8 * k0 + q];
                uint32_t aI1 = uInp[rB * FS + 8 * k0 + q];
                uint32_t aI2 = uInp[rA * FS + 8 * k0 + q + 4];
                uint32_t aI3 = uInp[rB * FS + 8 * k0 + q + 4];
                uint32_t aH0 = uHx[rA * FS + 8 * k0 + q];
                uint32_t aH1 = uHx[rB * FS + 8 * k0 + q];
                uint32_t aH2 = uHx[rA * FS + 8 * k0 + q + 4];
                uint32_t aH3 = uHx[rB * FS + 8 * k0 + q + 4];
                #pragma unroll
                for (int j = 0; j < 2; j++) {
                    int brow = c * 4352 + (nq + 8 * j + g) * FS + 8 * k0 + q;
                    uint32_t b0 = uWih[brow], b1 = uWih[brow + 4];
                    mma_tf32(accI[c][j][0], accI[c][j][1], accI[c][j][2], accI[c][j][3],
                             aI0, aI1, aI2, aI3, b0, b1);
                    uint32_t c0 = uWhh[brow], c1 = uWhh[brow + 4];
                    mma_tf32(accH[c][j][0], accH[c][j][1], accH[c][j][2], accH[c][j][3],
                             aH0, aH1, aH2, aH3, c0, c1);
                }
            }
        }

        // ---- instance-norm stats ----
        {
            float sIA = 0.f, qIA = 0.f, sIB = 0.f, qIB = 0.f;
            float sHA = 0.f, qHA = 0.f, sHB = 0.f, qHB = 0.f;
            #pragma unroll
            for (int c = 0; c < 3; c++)
                #pragma unroll
                for (int j = 0; j < 2; j++) {
                    float a0 = accI[c][j][0], a1 = accI[c][j][1];
                    float a2 = accI[c][j][2], a3 = accI[c][j][3];
                    sIA += a0 + a1; qIA += a0 * a0 + a1 * a1;
                    sIB += a2 + a3; qIB += a2 * a2 + a3 * a3;
                    float h0 = accH[c][j][0], h1 = accH[c][j][1];
                    float h2 = accH[c][j][2], h3 = accH[c][j][3];
                    sHA += h0 + h1; qHA += h0 * h0 + h1 * h1;
                    sHB += h2 + h3; qHB += h2 * h2 + h3 * h3;
                }
            #pragma unroll
            for (int m = 1; m <= 2; m <<= 1) {
                sIA += __shfl_xor_sync(0xffffffffu, sIA, m);
                qIA += __shfl_xor_sync(0xffffffffu, qIA, m);
                sIB += __shfl_xor_sync(0xffffffffu, sIB, m);
                qIB += __shfl_xor_sync(0xffffffffu, qIB, m);
                sHA += __shfl_xor_sync(0xffffffffu, sHA, m);
                qHA += __shfl_xor_sync(0xffffffffu, qHA, m);
                sHB += __shfl_xor_sync(0xffffffffu, sHB, m);
                qHB += __shfl_xor_sync(0xffffffffu, qHB, m);
            }
            if (q == 0) {
                float* rdA = sRed + (qt * 64 + rA) * 4;
                rdA[0] = sIA; rdA[1] = qIA; rdA[2] = sHA; rdA[3] = qHA;
                float* rdB = sRed + (qt * 64 + rB) * 4;
                rdB[0] = sIB; rdB[1] = qIB; rdB[2] = sHB; rdB[3] = qHB;
            }
        }
        __syncthreads();
        if (tx < 64) {
            float sI = 0.f, qI = 0.f, sH = 0.f, qH = 0.f;
            #pragma unroll
            for (int qt2 = 0; qt2 < 4; qt2++) {
                const float* rd = sRed + (qt2 * 64 + tx) * 4;
                sI += rd[0]; qI += rd[1]; sH += rd[2]; qH += rd[3];
            }
            float muI = sI * (1.f / 192.f);
            float varI = qI * (1.f / 192.f) - muI * muI;
            float muH = sH * (1.f / 192.f);
            float varH = qH * (1.f / 192.f) - muH * muH;
            sStat[tx * 4 + 0] = muI;
            sStat[tx * 4 + 1] = rsqrtf(varI + 1e-5f);
            sStat[tx * 4 + 2] = muH;
            sStat[tx * 4 + 3] = rsqrtf(varH + 1e-5f);
        }
        __syncthreads();

        // ---- gates + stage result (overwrites uInp region) ----
        {
            float muIA = sStat[rA * 4 + 0], rsIA = sStat[rA * 4 + 1];
            float muHA = sStat[rA * 4 + 2], rsHA = sStat[rA * 4 + 3];
            float muIB = sStat[rB * 4 + 0], rsIB = sStat[rB * 4 + 1];
            float muHB = sStat[rB * 4 + 2], rsHB = sStat[rB * 4 + 3];
            #pragma unroll
            for (int j = 0; j < 2; j++) {
                #pragma unroll
                for (int v = 0; v < 2; v++) {
                    int cb = nq + 8 * j + 2 * q + v;
                    float b_r = sBih[cb],       c_r = sBhh[cb];
                    float b_i = sBih[64 + cb],  c_i = sBhh[64 + cb];
                    float b_n = sBih[128 + cb], c_n = sBhh[128 + cb];
                    {
                        float i_r = (accI[0][j][v] - muIA) * rsIA;
                        float i_i = (accI[1][j][v] - muIA) * rsIA;
                        float i_n = (accI[2][j][v] - muIA) * rsIA;
                        float h_r = (accH[0][j][v] - muHA) * rsHA;
                        float h_i = (accH[1][j][v] - muHA) * rsHA;
                        float h_n = (accH[2][j][v] - muHA) * rsHA;
                        float r  = sigm(i_r + b_r + h_r + c_r);
                        float z  = sigm(i_i + b_i + h_i + c_i);
                        float ng = tanhf(i_n + b_n + r * (h_n + c_n));
                        float hxo = sHx32[rA * FS + cb];
                        sOut[rA * FS + cb] = ng + z * (hxo - ng);
                    }
                    {
                        float i_r = (accI[0][j][v + 2] - muIB) * rsIB;
                        float i_i = (accI[1][j][v + 2] - muIB) * rsIB;
                        float i_n = (accI[2][j][v + 2] - muIB) * rsIB;
                        float h_r = (accH[0][j][v + 2] - muHB) * rsHB;
                        float h_i = (accH[1][j][v + 2] - muHB) * rsHB;
                        float h_n = (accH[2][j][v + 2] - muHB) * rsHB;
                        float r  = sigm(i_r + b_r + h_r + c_r);
                        float z  = sigm(i_i + b_i + h_i + c_i);
                        float ng = tanhf(i_n + b_n + r * (h_n + c_n));
                        float hxo = sHx32[rB * FS + cb];
                        sOut[rB * FS + cb] = ng + z * (hxo - ng);
                    }
                }
            }
        }
        __syncthreads();

        // ---- coalesced write of new hx ----
        for (int idx = tx; idx < 4096; idx += 512) {
            int n = idx >> 6, k = idx & 63;
            if (n0 + n < N)
                out[(size_t)(n0 + n) * 256 + toff + 64 + k] = sOut[n * FS + k];
        }
    }
}

// ---------------- launcher ----------------
extern "C" void kernel_launch(void* const* d_in, const int* in_sizes, int n_in,
                              void* d_out, int out_size)
{
    const float* hx  = (const float*)d_in[0];
    const void*  eix = d_in[1];
    const float* ef  = (const float*)d_in[2];
    const float* fW1 = (const float*)d_in[3];
    const float* fb1 = (const float*)d_in[4];
    const float* fW2 = (const float*)d_in[5];
    const float* fb2 = (const float*)d_in[6];
    const float* fW3 = (const float*)d_in[7];
    const float* fb3 = (const float*)d_in[8];
    const float* Wih = (const float*)d_in[9];
    const float* Whh = (const float*)d_in[10];
    const float* bih = (const float*)d_in[11];
    const float* bhh = (const float*)d_in[12];
    const float* Wig = (const float*)d_in[13];
    const float* big = (const float*)d_in[14];
    float* out = (float*)d_out;

    const int N = in_sizes[0] / 64;
    const int E = in_sizes[2] / 13;
    const int nb = (N + 1023) / 1024;

    cudaFuncSetAttribute(fnet_mma_kernel, cudaFuncAttributeMaxDynamicSharedMemorySize, FNET_SMEM);
    cudaFuncSetAttribute(node_mma_kernel, cudaFuncAttributeMaxDynamicSharedMemorySize, NODE_SMEM);

    prep_kernel<<<(12288 + 255) / 256, 256>>>(fW1, fW2, fW3, Wig, Wih, Whh, (const int*)eix);
    copy_hx_kernel<<<(N * 64 + 255) / 256, 256>>>(hx, out, N);
    degi_kernel<<<(E + 255) / 256, 256>>>(eix, E);
    scan1_kernel<<<nb, 256>>>(N);
    scan3_kernel<<<(N + 255) / 256, 256>>>(N);
    bin_kernel<<<(E + 255) / 256, 256>>>(eix, E);
    fnet_mma_kernel<<<148, 512, FNET_SMEM>>>(ef, fb1, fb2, fb3, E);

    for (int t = 0; t < 3; t++)
        node_mma_kernel<<<148, 512, NODE_SMEM>>>(out, bih, bhh, big, t, N);
}

// round 14
// speedup vs baseline: 1.3802x; 1.0116x over previous
#include <cuda_runtime.h>
#include <cuda_fp16.h>
#include <cstdint>

#define NN 100000
#define NE 1250000
#define FS 68

// ---------------- device scratch (no allocs allowed) ----------------
__device__ __align__(16) uint32_t g_wp2[(size_t)NE * 32]; // per-edge weights as half2, BINNED by dst
__device__ int g_srcp[NE];                               // src node per binned position
__device__ int g_invperm[NE];                            // edge -> binned position
__device__ int g_degi[NN];
__device__ int g_start[NN];
__device__ int g_cursor[NN];
__device__ int g_bsum[128];
__device__ int g_tilq[4];                                // persistent-kernel tile queues
__device__ unsigned g_barc;                              // grid barrier counter
__device__ int g_idx64;

// pre-converted tf32 weights
__device__ uint32_t g_fw1u[1024];    // [64][16] padded
__device__ uint32_t g_fw2u[4096];
__device__ uint32_t g_fw3u[4096];
__device__ uint32_t g_wigu[4096];
__device__ uint32_t g_wihu[12288];
__device__ uint32_t g_whhu[12288];

__device__ __forceinline__ float sigm(float x) { return 1.f / (1.f + expf(-x)); }

__device__ __forceinline__ uint32_t f2tf32(float x) {
    uint32_t u;
    asm("cvt.rna.tf32.f32 %0, %1;" : "=r"(u) : "f"(x));
    return u;
}

// D[m][n] = sum_k A[m][k] * W[n][k], m16n8k8 tf32
__device__ __forceinline__ void mma_tf32(float& c0, float& c1, float& c2, float& c3,
                                         uint32_t a0, uint32_t a1, uint32_t a2, uint32_t a3,
                                         uint32_t b0, uint32_t b1)
{
    asm volatile("mma.sync.aligned.m16n8k8.row.col.f32.tf32.tf32.f32 "
                 "{%0,%1,%2,%3}, {%4,%5,%6,%7}, {%8,%9}, {%0,%1,%2,%3};"
                 : "+f"(c0), "+f"(c1), "+f"(c2), "+f"(c3)
                 : "r"(a0), "r"(a1), "r"(a2), "r"(a3), "r"(b0), "r"(b1));
}

// ---------------- launch 1: prep (+ edge_index dtype detect in block 0) ----------------
__global__ void prep_kernel(const float* __restrict__ fW1, const float* __restrict__ fW2,
                            const float* __restrict__ fW3, const float* __restrict__ Wig,
                            const float* __restrict__ Wih, const float* __restrict__ Whh,
                            const int* __restrict__ eidx_raw)
{
    int i = blockIdx.x * blockDim.x + threadIdx.x;
    if (blockIdx.x == 0) {
        __shared__ int nz;
        if (threadIdx.x == 0) nz = 0;
        __syncthreads();
        if (eidx_raw[2 * threadIdx.x + 1] != 0) atomicOr(&nz, 1);
        __syncthreads();
        if (threadIdx.x == 0) g_idx64 = (nz == 0) ? 1 : 0;
    }
    if (i < 1024) {
        int o = i >> 4, k = i & 15;
        g_fw1u[i] = (k < 13) ? f2tf32(fW1[o * 13 + k]) : 0u;
    }
    if (i < 4096) {
        g_fw2u[i] = f2tf32(fW2[i]);
        g_fw3u[i] = f2tf32(fW3[i]);
        g_wigu[i] = f2tf32(Wig[i]);
    }
    if (i < 12288) {
        g_wihu[i] = f2tf32(Wih[i]);
        g_whhu[i] = f2tf32(Whh[i]);
    }
}

// ---------------- launch 2: copy hx + zero counters/queues/barrier ----------------
__global__ void copy_hx_kernel(const float* __restrict__ hx, float* __restrict__ out, int N) {
    int idx = blockIdx.x * blockDim.x + threadIdx.x;
    if (idx < N) { g_degi[idx] = 0; g_cursor[idx] = 0; }
    if (idx < 4) g_tilq[idx] = 0;
    if (idx == 0) g_barc = 0u;
    if (idx < N * 64) {
        int n = idx >> 6, k = idx & 63;
        out[(size_t)n * 256 + k] = hx[idx];
    }
}

// ---------------- launch 3: degree count ----------------
__global__ void degi_kernel(const void* __restrict__ eidx, int E) {
    int e = blockIdx.x * blockDim.x + threadIdx.x;
    if (e >= E) return;
    int d;
    if (g_idx64) d = (int)((const long long*)eidx)[e];
    else         d = ((const int*)eidx)[e];
    atomicAdd(&g_degi[d], 1);
}

// ---------------- launch 4: per-1024-element block scan ----------------
__global__ void scan1_kernel(int N) {
    __shared__ int sS[256];
    int b = blockIdx.x, tid = threadIdx.x;
    int base = b * 1024 + tid * 4;
    int v0 = (base + 0 < N) ? g_degi[base + 0] : 0;
    int v1 = (base + 1 < N) ? g_degi[base + 1] : 0;
    int v2 = (base + 2 < N) ? g_degi[base + 2] : 0;
    int v3 = (base + 3 < N) ? g_degi[base + 3] : 0;
    int tsum = v0 + v1 + v2 + v3;
    sS[tid] = tsum;
    __syncthreads();
    for (int off = 1; off < 256; off <<= 1) {
        int x = (tid >= off) ? sS[tid - off] : 0;
        __syncthreads();
        sS[tid] += x;
        __syncthreads();
    }
    int excl = sS[tid] - tsum;
    if (base + 0 < N) g_start[base + 0] = excl;
    if (base + 1 < N) g_start[base + 1] = excl + v0;
    if (base + 2 < N) g_start[base + 2] = excl + v0 + v1;
    if (base + 3 < N) g_start[base + 3] = excl + v0 + v1 + v2;
    if (tid == 255) g_bsum[b] = sS[255];
}

// ---------------- launch 5: add cross-block prefix (inline) ----------------
__global__ void scan3_kernel(int N) {
    __shared__ int soff;
    int b = blockIdx.x;
    int grp = b >> 2;
    if (threadIdx.x < 32) {
        int acc = 0;
        for (int j = threadIdx.x; j < grp; j += 32) acc += g_bsum[j];
        #pragma unroll
        for (int m = 16; m; m >>= 1) acc += __shfl_xor_sync(0xffffffffu, acc, m);
        if (threadIdx.x == 0) soff = acc;
    }
    __syncthreads();
    int i = b * 256 + threadIdx.x;
    if (i < N) g_start[i] += soff;
}

// ---------------- launch 6: bin edges by destination ----------------
__global__ void bin_kernel(const void* __restrict__ eidx, int E) {
    int e = blockIdx.x * blockDim.x + threadIdx.x;
    if (e >= E) return;
    int d, s;
    if (g_idx64) {
        const long long* p = (const long long*)eidx;
        d = (int)p[e]; s = (int)p[E + e];
    } else {
        const int* p = (const int*)eidx;
        d = p[e]; s = p[E + e];
    }
    int pos = g_start[d] + atomicAdd(&g_cursor[d], 1);
    g_invperm[e] = pos;
    g_srcp[pos] = s;
}

// ---------------- launch 7: PERSISTENT fnet via mma.sync tf32 ----------------
#define F_X   0
#define F_W1  (256 * FS)
#define F_W2  (F_W1 + 64 * FS)
#define F_W3  (F_W2 + 64 * FS)
#define F_B   (F_W3 + 64 * FS)
#define F_P   (F_B + 192)
#define FNET_FLOATS (F_P + 256)
#define FNET_SMEM (FNET_FLOATS * 4)

__global__ __launch_bounds__(512, 1) void fnet_mma_kernel(
    const float* __restrict__ ef,
    const float* __restrict__ fb1, const float* __restrict__ fb2,
    const float* __restrict__ fb3, int E)
{
    extern __shared__ float sm[];
    uint32_t* uX  = (uint32_t*)(sm + F_X);
    uint32_t* uW1 = (uint32_t*)(sm + F_W1);
    uint32_t* uW2 = (uint32_t*)(sm + F_W2);
    uint32_t* uW3 = (uint32_t*)(sm + F_W3);
    float*    sB  = sm + F_B;
    int*      sP  = (int*)(sm + F_P);

    const int tid = threadIdx.x;
    const int wid = tid >> 5, lane = tid & 31;
    const int g = lane >> 2, q = lane & 3;
    const int r0 = wid * 16;
    const int rA = r0 + g, rB = r0 + 8 + g;
    const int ntiles = (E + 255) / 256;

    for (int idx = tid; idx < 1024; idx += 512) {
        int o = idx >> 4, k = idx & 15;
        uW1[o * FS + k] = g_fw1u[idx];
    }
    for (int idx = tid; idx < 4096; idx += 512) {
        int o = idx >> 6, k = idx & 63;
        uW2[o * FS + k] = g_fw2u[idx];
        uW3[o * FS + k] = g_fw3u[idx];
    }
    if (tid < 64) { sB[tid] = fb1[tid]; sB[64 + tid] = fb2[tid]; sB[128 + tid] = fb3[tid]; }

    for (int tile = blockIdx.x; tile < ntiles; tile += 148) {
        const int e0 = tile * 256;

        for (int idx = tid; idx < 256 * 16; idx += 512) {
            int e = idx >> 4, k = idx & 15;
            float v = (k < 13 && e0 + e < E) ? ef[(size_t)(e0 + e) * 13 + k] : 0.f;
            uX[e * FS + k] = f2tf32(v);
        }
        if (tid < 256) sP[tid] = (e0 + tid < E) ? g_invperm[e0 + tid] : -1;
        __syncthreads();

        float acc[8][4];

        // ---- layer 1 (K = 16) ----
        #pragma unroll
        for (int j = 0; j < 8; j++) {
            int cb = j * 8 + 2 * q;
            acc[j][0] = acc[j][2] = sB[cb];
            acc[j][1] = acc[j][3] = sB[cb + 1];
        }
        #pragma unroll
        for (int k0 = 0; k0 < 2; k0++) {
            uint32_t a0 = uX[rA * FS + 8 * k0 + q];
            uint32_t a1 = uX[rB * FS + 8 * k0 + q];
            uint32_t a2 = uX[rA * FS + 8 * k0 + q + 4];
            uint32_t a3 = uX[rB * FS + 8 * k0 + q + 4];
            #pragma unroll
            for (int j = 0; j < 8; j++) {
                uint32_t b0 = uW1[(8 * j + g) * FS + 8 * k0 + q];
                uint32_t b1 = uW1[(8 * j + g) * FS + 8 * k0 + q + 4];
                mma_tf32(acc[j][0], acc[j][1], acc[j][2], acc[j][3], a0, a1, a2, a3, b0, b1);
            }
        }
        #pragma unroll
        for (int j = 0; j < 8; j++) {
            int cb = j * 8 + 2 * q;
            uX[rA * FS + cb]     = f2tf32(fmaxf(acc[j][0], 0.f));
            uX[rA * FS + cb + 1] = f2tf32(fmaxf(acc[j][1], 0.f));
            uX[rB * FS + cb]     = f2tf32(fmaxf(acc[j][2], 0.f));
            uX[rB * FS + cb + 1] = f2tf32(fmaxf(acc[j][3], 0.f));
        }
        __syncwarp();

        // ---- layer 2 (K = 64, relu) ----
        #pragma unroll
        for (int j = 0; j < 8; j++) {
            int cb = j * 8 + 2 * q;
            acc[j][0] = acc[j][2] = sB[64 + cb];
            acc[j][1] = acc[j][3] = sB[64 + cb + 1];
        }
        #pragma unroll
        for (int k0 = 0; k0 < 8; k0++) {
            uint32_t a0 = uX[rA * FS + 8 * k0 + q];
            uint32_t a1 = uX[rB * FS + 8 * k0 + q];
            uint32_t a2 = uX[rA * FS + 8 * k0 + q + 4];
            uint32_t a3 = uX[rB * FS + 8 * k0 + q + 4];
            #pragma unroll
            for (int j = 0; j < 8; j++) {
                uint32_t b0 = uW2[(8 * j + g) * FS + 8 * k0 + q];
                uint32_t b1 = uW2[(8 * j + g) * FS + 8 * k0 + q + 4];
                mma_tf32(acc[j][0], acc[j][1], acc[j][2], acc[j][3], a0, a1, a2, a3, b0, b1);
            }
        }
        __syncwarp();
        #pragma unroll
        for (int j = 0; j < 8; j++) {
            int cb = j * 8 + 2 * q;
            uX[rA * FS + cb]     = f2tf32(fmaxf(acc[j][0], 0.f));
            uX[rA * FS + cb + 1] = f2tf32(fmaxf(acc[j][1], 0.f));
            uX[rB * FS + cb]     = f2tf32(fmaxf(acc[j][2], 0.f));
            uX[rB * FS + cb + 1] = f2tf32(fmaxf(acc[j][3], 0.f));
        }
        __syncwarp();

        // ---- layer 3 (K = 64, no relu) ----
        #pragma unroll
        for (int j = 0; j < 8; j++) {
            int cb = j * 8 + 2 * q;
            acc[j][0] = acc[j][2] = sB[128 + cb];
            acc[j][1] = acc[j][3] = sB[128 + cb + 1];
        }
        #pragma unroll
        for (int k0 = 0; k0 < 8; k0++) {
            uint32_t a0 = uX[rA * FS + 8 * k0 + q];
            uint32_t a1 = uX[rB * FS + 8 * k0 + q];
            uint32_t a2 = uX[rA * FS + 8 * k0 + q + 4];
            uint32_t a3 = uX[rB * FS + 8 * k0 + q + 4];
            #pragma unroll
            for (int j = 0; j < 8; j++) {
                uint32_t b0 = uW3[(8 * j + g) * FS + 8 * k0 + q];
                uint32_t b1 = uW3[(8 * j + g) * FS + 8 * k0 + q + 4];
                mma_tf32(acc[j][0], acc[j][1], acc[j][2], acc[j][3], a0, a1, a2, a3, b0, b1);
            }
        }
        __syncwarp();

        // ---- epilogue: pack half2 in-place, store 128B rows to binned positions ----
        {
            uint32_t* sH = (uint32_t*)(sm + F_X);
            #pragma unroll
            for (int j = 0; j < 8; j++) {
                int cw = j * 4 + q;
                __half2 hA = __floats2half2_rn(acc[j][0], acc[j][1]);
                __half2 hB = __floats2half2_rn(acc[j][2], acc[j][3]);
                sH[rA * FS + cw] = *(uint32_t*)&hA;
                sH[rB * FS + cw] = *(uint32_t*)&hB;
            }
        }
        __syncthreads();
        {
            const uint32_t* sH = (const uint32_t*)(sm + F_X);
            #pragma unroll
            for (int i = 0; i < 4; i++) {
                int gidx = i * 512 + tid;
                int r = gidx >> 3, c = gidx & 7;
                int dst = sP[r];
                if (dst >= 0)
                    ((uint4*)g_wp2)[(size_t)dst * 8 + c] = *(const uint4*)(sH + r * FS + c * 4);
            }
        }
        __syncthreads();
    }
}

// ---------------- launch 8: persistent fused agg + GRU, ALL 3 repeats in one launch ----------------
#define P_WIG  0
#define P_WIH  (P_WIG + 64 * FS)          /* 4352  */
#define P_WHH  (P_WIH + 3 * 64 * FS)      /* 17408 */
#define P_BIG  (P_WHH + 3 * 64 * FS)      /* 30464 */
#define P_BIH  (P_BIG + 64)
#define P_BHH  (P_BIH + 192)
#define P_HX32 (P_BHH + 192)              /* 30912 */
#define P_UHX  (P_HX32 + 64 * FS)
#define P_UINP (P_UHX + 64 * FS)
#define P_AGG  (P_UINP + 64 * FS)
#define P_RED  (P_AGG + 64 * FS)          /* 48320 */
#define P_STAT (P_RED + 1024)
#define P_TIL  (P_STAT + 256)             /* 49600 */
#define NODE_FLOATS (P_TIL + 4)
#define NODE_SMEM (NODE_FLOATS * 4)       /* 198416 B */

__global__ __launch_bounds__(512, 1) void node_mma_kernel(
    float* __restrict__ out,
    const float* __restrict__ bih, const float* __restrict__ bhh,
    const float* __restrict__ big, int N)
{
    extern __shared__ float sm[];
    uint32_t* uWig  = (uint32_t*)(sm + P_WIG);
    uint32_t* uWih  = (uint32_t*)(sm + P_WIH);
    uint32_t* uWhh  = (uint32_t*)(sm + P_WHH);
    float*    sBig  = sm + P_BIG;
    float*    sBih  = sm + P_BIH;
    float*    sBhh  = sm + P_BHH;
    float*    sHx32 = sm + P_HX32;
    uint32_t* uHx   = (uint32_t*)(sm + P_UHX);
    uint32_t* uInp  = (uint32_t*)(sm + P_UINP);
    float*    sOut  = sm + P_UINP;
    float*    sAgg  = sm + P_AGG;
    float*    sRed  = sm + P_RED;
    float*    sStat = sm + P_STAT;
    int*      sTil  = (int*)(sm + P_TIL);

    const int tx = threadIdx.x;
    const int wid = tx >> 5, lane = tx & 31;
    const int g = lane >> 2, q = lane & 3;
    const int rowgrp = wid & 3, qt = wid >> 2;
    const int nq = qt * 16;
    const int rA = rowgrp * 16 + g, rB = rA + 8;
    const int ntiles = (N + 63) / 64;

    // ---- stage ALL weights + biases once ----
    for (int idx = tx; idx < 4096; idx += 512) {
        int o = idx >> 6, k = idx & 63;
        uWig[o * FS + k] = g_wigu[idx];
    }
    for (int idx = tx; idx < 12288; idx += 512) {
        int c = idx >> 12, r = idx & 4095;
        int o = r >> 6, k = r & 63;
        uWih[c * 4352 + o * FS + k] = g_wihu[idx];
        uWhh[c * 4352 + o * FS + k] = g_whhu[idx];
    }
    if (tx < 64)  sBig[tx] = big[tx];
    if (tx < 192) { sBih[tx] = bih[tx]; sBhh[tx] = bhh[tx]; }

    for (int t = 0; t < 3; t++) {
        const int toff = t * 64;

        for (;;) {
            if (tx == 0) sTil[0] = atomicAdd(&g_tilq[t], 1);
            __syncthreads();
            const int tile = sTil[0];
            if (tile >= ntiles) break;
            const int n0 = tile * 64;
            const int gnA = n0 + rA, gnB = n0 + rB;

            // ---- stage hx ----
            for (int idx = tx; idx < 4096; idx += 512) {
                int n = idx >> 6, k = idx & 63;
                float v = (n0 + n < N) ? out[(size_t)(n0 + n) * 256 + toff + k] : 0.f;
                sHx32[n * FS + k] = v;
                uHx[n * FS + k] = f2tf32(v);
            }

            // ---- in-block aggregation ----
            {
                const float* o_t = out + toff;
                const __half2* w2 = (const __half2*)g_wp2;
                #pragma unroll
                for (int u = 0; u < 4; u++) {
                    int ln = wid * 4 + u;
                    int gn = n0 + ln;
                    float ax = 0.f, ay = 0.f, bx = 0.f, by = 0.f;
                    if (gn < N) {
                        int start = g_start[gn];
                        int deg   = g_degi[gn];
                        int i = 0;
                        for (; i + 2 <= deg; i += 2) {
                            int p0 = start + i, p1 = start + i + 1;
                            int s0 = g_srcp[p0], s1 = g_srcp[p1];
                            float2 w0 = __half22float2(w2[(size_t)p0 * 32 + lane]);
                            float2 h0 = *(const float2*)(o_t + (size_t)s0 * 256 + 2 * lane);
                            float2 w1 = __half22float2(w2[(size_t)p1 * 32 + lane]);
                            float2 h1 = *(const float2*)(o_t + (size_t)s1 * 256 + 2 * lane);
                            ax += w0.x * h0.x; ay += w0.y * h0.y;
                            bx += w1.x * h1.x; by += w1.y * h1.y;
                        }
                        if (i < deg) {
                            int p0 = start + i;
                            int s0 = g_srcp[p0];
                            float2 w0 = __half22float2(w2[(size_t)p0 * 32 + lane]);
                            float2 h0 = *(const float2*)(o_t + (size_t)s0 * 256 + 2 * lane);
                            ax += w0.x * h0.x; ay += w0.y * h0.y;
                        }
                    }
                    sAgg[ln * FS + 2 * lane]     = ax + bx;
                    sAgg[ln * FS + 2 * lane + 1] = ay + by;
                }
            }
            __syncthreads();

            // ---- inp = sigmoid(hx @ Wig^T + big) * agg * invdeg ----
            {
                float aw[2][4];
                #pragma unroll
                for (int j = 0; j < 2; j++) {
                    int cb = nq + 8 * j + 2 * q;
                    aw[j][0] = aw[j][2] = sBig[cb];
                    aw[j][1] = aw[j][3] = sBig[cb + 1];
                }
                #pragma unroll
                for (int k0 = 0; k0 < 8; k0++) {
                    uint32_t a0 = uHx[rA * FS + 8 * k0 + q];
                    uint32_t a1 = uHx[rB * FS + 8 * k0 + q];
                    uint32_t a2 = uHx[rA * FS + 8 * k0 + q + 4];
                    uint32_t a3 = uHx[rB * FS + 8 * k0 + q + 4];
                    #pragma unroll
                    for (int j = 0; j < 2; j++) {
                        uint32_t b0 = uWig[(nq + 8 * j + g) * FS + 8 * k0 + q];
                        uint32_t b1 = uWig[(nq + 8 * j + g) * FS + 8 * k0 + q + 4];
                        mma_tf32(aw[j][0], aw[j][1], aw[j][2], aw[j][3], a0, a1, a2, a3, b0, b1);
                    }
                }
                float invA = (gnA < N) ? 1.f / fmaxf((float)g_degi[gnA], 1.f) : 0.f;
                float invB = (gnB < N) ? 1.f / fmaxf((float)g_degi[gnB], 1.f) : 0.f;
                #pragma unroll
                for (int j = 0; j < 2; j++) {
                    int cb = nq + 8 * j + 2 * q;
                    uInp[rA * FS + cb]     = f2tf32(sigm(aw[j][0]) * sAgg[rA * FS + cb]     * invA);
                    uInp[rA * FS + cb + 1] = f2tf32(sigm(aw[j][1]) * sAgg[rA * FS + cb + 1] * invA);
                    uInp[rB * FS + cb]     = f2tf32(sigm(aw[j][2]) * sAgg[rB * FS + cb]     * invB);
                    uInp[rB * FS + cb + 1] = f2tf32(sigm(aw[j][3]) * sAgg[rB * FS + cb + 1] * invB);
                }
            }
            __syncthreads();

            // ---- GI = inp @ Wih^T ; GH = hx @ Whh^T : resident weights ----
            float accI[3][2][4], accH[3][2][4];
            #pragma unroll
            for (int c = 0; c < 3; c++) {
                #pragma unroll
                for (int j = 0; j < 2; j++)
                    #pragma unroll
                    for (int v = 0; v < 4; v++) { accI[c][j][v] = 0.f; accH[c][j][v] = 0.f; }
                #pragma unroll
                for (int k0 = 0; k0 < 8; k0++) {
                    uint32_t aI0 = uInp[rA * FS + 8 * k0 + q];
                    uint32_t aI1 = uInp[rB * FS + 8 * k0 + q];
                    uint32_t aI2 = uInp[rA * FS + 8 * k0 + q + 4];
                    uint32_t aI3 = uInp[rB * FS + 8 * k0 + q + 4];
                    uint32_t aH0 = uHx[rA * FS + 8 * k0 + q];
                    uint32_t aH1 = uHx[rB * FS + 8 * k0 + q];
                    uint32_t aH2 = uHx[rA * FS + 8 * k0 + q + 4];
                    uint32_t aH3 = uHx[rB * FS + 8 * k0 + q + 4];
                    #pragma unroll
                    for (int j = 0; j < 2; j++) {
                        int brow = c * 4352 + (nq + 8 * j + g) * FS + 8 * k0 + q;
                        uint32_t b0 = uWih[brow], b1 = uWih[brow + 4];
                        mma_tf32(accI[c][j][0], accI[c][j][1], accI[c][j][2], accI[c][j][3],
                                 aI0, aI1, aI2, aI3, b0, b1);
                        uint32_t c0 = uWhh[brow], c1 = uWhh[brow + 4];
                        mma_tf32(accH[c][j][0], accH[c][j][1], accH[c][j][2], accH[c][j][3],
                                 aH0, aH1, aH2, aH3, c0, c1);
                    }
                }
            }

            // ---- instance-norm stats ----
            {
                float sIA = 0.f, qIA = 0.f, sIB = 0.f, qIB = 0.f;
                float sHA = 0.f, qHA = 0.f, sHB = 0.f, qHB = 0.f;
                #pragma unroll
                for (int c = 0; c < 3; c++)
                    #pragma unroll
                    for (int j = 0; j < 2; j++) {
                        float a0 = accI[c][j][0], a1 = accI[c][j][1];
                        float a2 = accI[c][j][2], a3 = accI[c][j][3];
                        sIA += a0 + a1; qIA += a0 * a0 + a1 * a1;
                        sIB += a2 + a3; qIB += a2 * a2 + a3 * a3;
                        float h0 = accH[c][j][0], h1 = accH[c][j][1];
                        float h2 = accH[c][j][2], h3 = accH[c][j][3];
                        sHA += h0 + h1; qHA += h0 * h0 + h1 * h1;
                        sHB += h2 + h3; qHB += h2 * h2 + h3 * h3;
                    }
                #pragma unroll
                for (int m = 1; m <= 2; m <<= 1) {
                    sIA += __shfl_xor_sync(0xffffffffu, sIA, m);
                    qIA += __shfl_xor_sync(0xffffffffu, qIA, m);
                    sIB += __shfl_xor_sync(0xffffffffu, sIB, m);
                    qIB += __shfl_xor_sync(0xffffffffu, qIB, m);
                    sHA += __shfl_xor_sync(0xffffffffu, sHA, m);
                    qHA += __shfl_xor_sync(0xffffffffu, qHA, m);
                    sHB += __shfl_xor_sync(0xffffffffu, sHB, m);
                    qHB += __shfl_xor_sync(0xffffffffu, qHB, m);
                }
                if (q == 0) {
                    float* rdA = sRed + (qt * 64 + rA) * 4;
                    rdA[0] = sIA; rdA[1] = qIA; rdA[2] = sHA; rdA[3] = qHA;
                    float* rdB = sRed + (qt * 64 + rB) * 4;
                    rdB[0] = sIB; rdB[1] = qIB; rdB[2] = sHB; rdB[3] = qHB;
                }
            }
            __syncthreads();
            if (tx < 64) {
                float sI = 0.f, qI = 0.f, sH = 0.f, qH = 0.f;
                #pragma unroll
                for (int qt2 = 0; qt2 < 4; qt2++) {
                    const float* rd = sRed + (qt2 * 64 + tx) * 4;
                    sI += rd[0]; qI += rd[1]; sH += rd[2]; qH += rd[3];
                }
                float muI = sI * (1.f / 192.f);
                float varI = qI * (1.f / 192.f) - muI * muI;
                float muH = sH * (1.f / 192.f);
                float varH = qH * (1.f / 192.f) - muH * muH;
                sStat[tx * 4 + 0] = muI;
                sStat[tx * 4 + 1] = rsqrtf(varI + 1e-5f);
                sStat[tx * 4 + 2] = muH;
                sStat[tx * 4 + 3] = rsqrtf(varH + 1e-5f);
            }
            __syncthreads();

            // ---- gates + stage result ----
            {
                float muIA = sStat[rA * 4 + 0], rsIA = sStat[rA * 4 + 1];
                float muHA = sStat[rA * 4 + 2], rsHA = sStat[rA * 4 + 3];
                float muIB = sStat[rB * 4 + 0], rsIB = sStat[rB * 4 + 1];
                float muHB = sStat[rB * 4 + 2], rsHB = sStat[rB * 4 + 3];
                #pragma unroll
                for (int j = 0; j < 2; j++) {
                    #pragma unroll
                    for (int v = 0; v < 2; v++) {
                        int cb = nq + 8 * j + 2 * q + v;
                        float b_r = sBih[cb],       c_r = sBhh[cb];
                        float b_i = sBih[64 + cb],  c_i = sBhh[64 + cb];
                        float b_n = sBih[128 + cb], c_n = sBhh[128 + cb];
                        {
                            float i_r = (accI[0][j][v] - muIA) * rsIA;
                            float i_i = (accI[1][j][v] - muIA) * rsIA;
                            float i_n = (accI[2][j][v] - muIA) * rsIA;
                            float h_r = (accH[0][j][v] - muHA) * rsHA;
                            float h_i = (accH[1][j][v] - muHA) * rsHA;
                            float h_n = (accH[2][j][v] - muHA) * rsHA;
                            float r  = sigm(i_r + b_r + h_r + c_r);
                            float z  = sigm(i_i + b_i + h_i + c_i);
                            float ng = tanhf(i_n + b_n + r * (h_n + c_n));
                            float hxo = sHx32[rA * FS + cb];
                            sOut[rA * FS + cb] = ng + z * (hxo - ng);
                        }
                        {
                            float i_r = (accI[0][j][v + 2] - muIB) * rsIB;
                            float i_i = (accI[1][j][v + 2] - muIB) * rsIB;
                            float i_n = (accI[2][j][v + 2] - muIB) * rsIB;
                            float h_r = (accH[0][j][v + 2] - muHB) * rsHB;
                            float h_i = (accH[1][j][v + 2] - muHB) * rsHB;
                            float h_n = (accH[2][j][v + 2] - muHB) * rsHB;
                            float r  = sigm(i_r + b_r + h_r + c_r);
                            float z  = sigm(i_i + b_i + h_i + c_i);
                            float ng = tanhf(i_n + b_n + r * (h_n + c_n));
                            float hxo = sHx32[rB * FS + cb];
                            sOut[rB * FS + cb] = ng + z * (hxo - ng);
                        }
                    }
                }
            }
            __syncthreads();

            // ---- coalesced write of new hx ----
            for (int idx = tx; idx < 4096; idx += 512) {
                int n = idx >> 6, k = idx & 63;
                if (n0 + n < N)
                    out[(size_t)(n0 + n) * 256 + toff + 64 + k] = sOut[n * FS + k];
            }
        }

        // ---- software grid barrier between repeats (all 148 blocks co-resident) ----
        if (t < 2) {
            __threadfence();
            __syncthreads();
            if (tx == 0) {
                atomicAdd(&g_barc, 1u);
                unsigned target = 148u * (unsigned)(t + 1);
                while (atomicAdd(&g_barc, 0u) < target) __nanosleep(128);
            }
            __syncthreads();
            __threadfence();
        }
    }
}

// ---------------- launcher ----------------
extern "C" void kernel_launch(void* const* d_in, const int* in_sizes, int n_in,
                              void* d_out, int out_size)
{
    const float* hx  = (const float*)d_in[0];
    const void*  eix = d_in[1];
    const float* ef  = (const float*)d_in[2];
    const float* fW1 = (const float*)d_in[3];
    const float* fb1 = (const float*)d_in[4];
    const float* fW2 = (const float*)d_in[5];
    const float* fb2 = (const float*)d_in[6];
    const float* fW3 = (const float*)d_in[7];
    const float* fb3 = (const float*)d_in[8];
    const float* Wih = (const float*)d_in[9];
    const float* Whh = (const float*)d_in[10];
    const float* bih = (const float*)d_in[11];
    const float* bhh = (const float*)d_in[12];
    const float* Wig = (const float*)d_in[13];
    const float* big = (const float*)d_in[14];
    float* out = (float*)d_out;

    const int N = in_sizes[0] / 64;
    const int E = in_sizes[2] / 13;
    const int nb = (N + 1023) / 1024;

    cudaFuncSetAttribute(fnet_mma_kernel, cudaFuncAttributeMaxDynamicSharedMemorySize, FNET_SMEM);
    cudaFuncSetAttribute(node_mma_kernel, cudaFuncAttributeMaxDynamicSharedMemorySize, NODE_SMEM);

    prep_kernel<<<(12288 + 255) / 256, 256>>>(fW1, fW2, fW3, Wig, Wih, Whh, (const int*)eix);
    copy_hx_kernel<<<(N * 64 + 255) / 256, 256>>>(hx, out, N);
    degi_kernel<<<(E + 255) / 256, 256>>>(eix, E);
    scan1_kernel<<<nb, 256>>>(N);
    scan3_kernel<<<(N + 255) / 256, 256>>>(N);
    bin_kernel<<<(E + 255) / 256, 256>>>(eix, E);
    fnet_mma_kernel<<<148, 512, FNET_SMEM>>>(ef, fb1, fb2, fb3, E);

    node_mma_kernel<<<148, 512, NODE_SMEM>>>(out, bih, bhh, big, N);
}